// round 3
// baseline (speedup 1.0000x reference)
#include <cuda_runtime.h>

// ---------------- problem constants ----------------
static const int BSZ   = 64;
static const int SEQ   = 256;
static const int DIM   = 512;
static const int HID   = 512;
static const int DHID  = 1024;
static const int NGATE = 2048;              // 4*HID per direction
static const int MROWS = SEQ * BSZ;         // 16384
static const int CLS   = 5;
static const int NCTA  = 128;               // persistent CTAs (1/SM, <=148: all resident)
static const int WELEM = NGATE * DHID;      // 2097152 per direction

// ---------------- device scratch (float2 = {tf32_hi, tf32_lo} packed) ----------------
__device__ float2 g_xpk[(size_t)MROWS * DIM];        // split embeddings     64 MB
__device__ float2 g_wpk[2L * WELEM];                 // split weights        32 MB
__device__ float  g_gx [2L * SEQ * BSZ * NGATE];     // x-projection + bias 268 MB
__device__ float2 g_hpk[2 * 2 * BSZ * HID];          // [dir][parity][b][h] split h
__device__ float  g_hist[2L * SEQ * BSZ * HID];      // h history           67 MB
__device__ float  g_pooled[BSZ * HID];
__device__ unsigned g_cnt[SEQ];                      // grid-barrier counters

// ---------------- helpers ----------------
__device__ __forceinline__ float tf32_rna(float x) {
    unsigned u; asm("cvt.rna.tf32.f32 %0, %1;" : "=r"(u) : "f"(x));
    return __uint_as_float(u);
}
__device__ __forceinline__ unsigned fu(float x) { return __float_as_uint(x); }

// D(16x8,f32) += A(16x8 tf32 row) * B(8x8 tf32 col)
__device__ __forceinline__ void mma8(float* d, unsigned a0, unsigned a1, unsigned a2,
                                     unsigned a3, unsigned b0, unsigned b1) {
    asm volatile(
        "mma.sync.aligned.m16n8k8.row.col.f32.tf32.tf32.f32 "
        "{%0,%1,%2,%3},{%4,%5,%6,%7},{%8,%9},{%0,%1,%2,%3};\n"
        : "+f"(d[0]), "+f"(d[1]), "+f"(d[2]), "+f"(d[3])
        : "r"(a0), "r"(a1), "r"(a2), "r"(a3), "r"(b0), "r"(b1));
}

extern __shared__ char dynraw[];

// ---------------- kernel 0: zero h state + barrier counters ----------------
__global__ void k_zero() {
    int i = blockIdx.x * blockDim.x + threadIdx.x;
    if (i < 2 * 2 * BSZ * HID) g_hpk[i] = make_float2(0.0f, 0.0f);
    if (i < SEQ) g_cnt[i] = 0u;
}

// ---------------- kernel 1: split weights into tf32 hi/lo ----------------
__global__ void k_split(const float* __restrict__ fwdW, const float* __restrict__ bwdW) {
    size_t i = (size_t)blockIdx.x * 256 + threadIdx.x;   // over 2*WELEM
    float w = (i < (size_t)WELEM) ? fwdW[i] : bwdW[i - WELEM];
    float hi = tf32_rna(w);
    g_wpk[i] = make_float2(hi, tf32_rna(w - hi));
}

// ---------------- kernel 2: embedding gather + split ----------------
__global__ void k_gather(const int* __restrict__ x, const float* __restrict__ embed) {
    int sb = blockIdx.x;                 // sb = s*BSZ + b
    int b = sb & (BSZ - 1);
    int s = sb >> 6;
    int tok = x[b * SEQ + s];
    int c = threadIdx.x * 4;
    float4 v = *(const float4*)(embed + (size_t)tok * DIM + c);
    float2* dst = g_xpk + (size_t)sb * DIM + c;
    float h0 = tf32_rna(v.x); dst[0] = make_float2(h0, tf32_rna(v.x - h0));
    float h1 = tf32_rna(v.y); dst[1] = make_float2(h1, tf32_rna(v.y - h1));
    float h2 = tf32_rna(v.z); dst[2] = make_float2(h2, tf32_rna(v.z - h2));
    float h3 = tf32_rna(v.w); dst[3] = make_float2(h3, tf32_rna(v.w - h3));
}

// ---------------- kernel 3: x-projection GEMM (tf32 mma, 3-pass) ----------------
// C[m][n] = sum_k xs[m][k]*W(n)[k] + bias(n);  BM=128, BN=64, BK=32.
// 8 warps: 4x2 grid of 32x32 warp tiles.
static const int APstr = 132;   // float2 stride: (132*2)%32==8 -> conflict-free frags
static const int BPstr = 68;    // (68*2)%32==8
static const int GEMM_SMEM = (32 * APstr + 32 * BPstr) * (int)sizeof(float2);  // 51200

__global__ void __launch_bounds__(256, 2)
k_gemm_tc(const float* __restrict__ fwdb, const float* __restrict__ bwdb) {
    float2* Ap = (float2*)dynraw;          // [32][APstr]  (k-major)
    float2* Bp = Ap + 32 * APstr;          // [32][BPstr]

    const int tid = threadIdx.x, lane = tid & 31, wid = tid >> 5;
    const int group = lane >> 2, tig = lane & 3;
    const int mw = wid >> 1, nw = wid & 1;
    const int m0 = blockIdx.y * 128, n0 = blockIdx.x * 64;
    const int dir = n0 >> 11, ngbase = n0 & 2047;
    const float2* wbase = g_wpk + (size_t)dir * WELEM;
    const size_t dirbase = (size_t)dir * SEQ * BSZ * NGATE;

    const int arow = tid >> 1, ahalf = tid & 1;     // A staging: 128 rows x 2 halves
    const int brow = tid >> 2, bq = tid & 3;        // B staging: 64 rows x 4 quarters

    float acc[2][4][4];
#pragma unroll
    for (int i = 0; i < 2; i++)
#pragma unroll
        for (int t = 0; t < 4; t++)
#pragma unroll
            for (int r = 0; r < 4; r++) acc[i][t][r] = 0.0f;

    for (int k0 = 0; k0 < DIM; k0 += 32) {
        // stage A: Ap[k][m] <- g_xpk[m0+m][k0+k]
        const float4* asrc = (const float4*)(g_xpk + (size_t)(m0 + arow) * DIM + k0 + ahalf * 16);
#pragma unroll
        for (int q = 0; q < 8; q++) {
            float4 v = asrc[q];
            int kk = ahalf * 16 + q * 2;
            Ap[kk * APstr + arow]       = make_float2(v.x, v.y);
            Ap[(kk + 1) * APstr + arow] = make_float2(v.z, v.w);
        }
        // stage B: Bp[k][n] <- wpk[n0+n][k0+k]
        const float4* bsrc = (const float4*)(wbase + (size_t)(ngbase + brow) * DHID + k0 + bq * 8);
#pragma unroll
        for (int q = 0; q < 4; q++) {
            float4 v = bsrc[q];
            int kk = bq * 8 + q * 2;
            Bp[kk * BPstr + brow]       = make_float2(v.x, v.y);
            Bp[(kk + 1) * BPstr + brow] = make_float2(v.z, v.w);
        }
        __syncthreads();

#pragma unroll
        for (int k8 = 0; k8 < 4; k8++) {
            const int kb = k8 * 8;
            float2 A0[2], A1[2], A2[2], A3[2];
#pragma unroll
            for (int i = 0; i < 2; i++) {
                int mr = mw * 32 + i * 16 + group;
                A0[i] = Ap[(kb + tig) * APstr + mr];
                A1[i] = Ap[(kb + tig) * APstr + mr + 8];
                A2[i] = Ap[(kb + tig + 4) * APstr + mr];
                A3[i] = Ap[(kb + tig + 4) * APstr + mr + 8];
            }
            float2 B0[4], B1[4];
#pragma unroll
            for (int t = 0; t < 4; t++) {
                int nc = nw * 32 + t * 8 + group;
                B0[t] = Bp[(kb + tig) * BPstr + nc];
                B1[t] = Bp[(kb + tig + 4) * BPstr + nc];
            }
#pragma unroll
            for (int i = 0; i < 2; i++)
#pragma unroll
                for (int t = 0; t < 4; t++) {
                    mma8(acc[i][t], fu(A0[i].x), fu(A1[i].x), fu(A2[i].x), fu(A3[i].x),
                         fu(B0[t].x), fu(B1[t].x));
                    mma8(acc[i][t], fu(A0[i].x), fu(A1[i].x), fu(A2[i].x), fu(A3[i].x),
                         fu(B0[t].y), fu(B1[t].y));
                    mma8(acc[i][t], fu(A0[i].y), fu(A1[i].y), fu(A2[i].y), fu(A3[i].y),
                         fu(B0[t].x), fu(B1[t].x));
                }
        }
        __syncthreads();
    }

    // epilogue: add bias, write float2 pairs to g_gx[dir][m][ng]
    const float* bv = dir ? bwdb : fwdb;
#pragma unroll
    for (int i = 0; i < 2; i++) {
        int mrow = m0 + mw * 32 + i * 16 + group;
        size_t base0 = dirbase + (size_t)mrow * NGATE;
        size_t base1 = dirbase + (size_t)(mrow + 8) * NGATE;
#pragma unroll
        for (int t = 0; t < 4; t++) {
            int ng = ngbase + nw * 32 + t * 8 + 2 * tig;
            float2 bb = *(const float2*)(bv + ng);
            *(float2*)(g_gx + base0 + ng) = make_float2(acc[i][t][0] + bb.x, acc[i][t][1] + bb.y);
            *(float2*)(g_gx + base1 + ng) = make_float2(acc[i][t][2] + bb.x, acc[i][t][3] + bb.y);
        }
    }
}

// ---------------- kernel 4: persistent recurrence (tf32 mma, 3-pass) ----------------
// 128 CTAs: dir = bid>>6, unit block j0 = (bid&63)*8 -> 32 gate cols x 64 batch.
// Wh slice (split, packed) resident in smem; h read split-packed via L2.
static const int Wstr = 36;     // float2 stride: (36*2)%32==8 -> conflict-free B frags
static const int SPstr = 34;    // float stride for preact exchange
static const int RECUR_SMEM = HID * Wstr * (int)sizeof(float2) + BSZ * SPstr * (int)sizeof(float);

__global__ void __launch_bounds__(256, 1)
k_recur_tc() {
    float2* wsm = (float2*)dynraw;                 // [512][Wstr]
    float*  sp  = (float*)(wsm + HID * Wstr);      // [64][SPstr]

    const int bid = blockIdx.x;
    const int dir = bid >> 6;
    const int j0 = (bid & 63) * 8;
    const int tid = threadIdx.x, lane = tid & 31, wid = tid >> 5;
    const int group = lane >> 2, tig = lane & 3;
    const int mt = wid >> 1, nt = wid & 1;         // warp tile: m16 x n16
    const int b0 = mt * 16, nb = nt * 16;

    // ---- preload Wh slice (h-part: k offset DIM) once ----
    const float2* wd = g_wpk + (size_t)dir * WELEM;
#pragma unroll
    for (int i = 0; i < 64; i++) {
        int idx = i * 256 + tid;                   // 16384 = 32 cols x 512 k
        int n = idx >> 9, k = idx & 511;
        int col = (n >> 3) * HID + j0 + (n & 7);
        wsm[k * Wstr + n] = wd[(size_t)col * DHID + DIM + k];
    }
    __syncthreads();

    for (int t = 0; t < SEQ; t++) {
        const int s = dir ? (SEQ - 1 - t) : t;
        const float2* hpk = g_hpk + ((size_t)dir * 2 + (t & 1)) * (BSZ * HID);
        float2*       hnw = g_hpk + ((size_t)dir * 2 + ((t + 1) & 1)) * (BSZ * HID);

        // prefetch x-projections (independent of h) for the nonlinearity pass
        size_t gxbase = ((size_t)dir * SEQ + s) * BSZ * NGATE;
        float gxa[2][4];
#pragma unroll
        for (int u = 0; u < 2; u++) {
            int it = tid + u * 256, b = it >> 3, jj = it & 7;
#pragma unroll
            for (int g = 0; g < 4; g++)
                gxa[u][g] = g_gx[gxbase + (size_t)b * NGATE + g * HID + j0 + jj];
        }

        float acc[2][4];
#pragma unroll
        for (int t2 = 0; t2 < 2; t2++)
#pragma unroll
            for (int r = 0; r < 4; r++) acc[t2][r] = 0.0f;

#pragma unroll 8
        for (int k8 = 0; k8 < 64; k8++) {
            const int kk = k8 * 8;
            float2 a0 = __ldcg(hpk + (size_t)(b0 + group) * HID + kk + tig);
            float2 a1 = __ldcg(hpk + (size_t)(b0 + group + 8) * HID + kk + tig);
            float2 a2 = __ldcg(hpk + (size_t)(b0 + group) * HID + kk + tig + 4);
            float2 a3 = __ldcg(hpk + (size_t)(b0 + group + 8) * HID + kk + tig + 4);
#pragma unroll
            for (int t2 = 0; t2 < 2; t2++) {
                float2 B0 = wsm[(kk + tig) * Wstr + nb + t2 * 8 + group];
                float2 B1 = wsm[(kk + tig + 4) * Wstr + nb + t2 * 8 + group];
                mma8(acc[t2], fu(a0.x), fu(a1.x), fu(a2.x), fu(a3.x), fu(B0.x), fu(B1.x));
                mma8(acc[t2], fu(a0.x), fu(a1.x), fu(a2.x), fu(a3.x), fu(B0.y), fu(B1.y));
                mma8(acc[t2], fu(a0.y), fu(a1.y), fu(a2.y), fu(a3.y), fu(B0.x), fu(B1.x));
            }
        }

        // exchange preacts via smem (gates split across warp pairs)
#pragma unroll
        for (int t2 = 0; t2 < 2; t2++) {
            int nc = nb + t2 * 8 + 2 * tig;
            *(float2*)(sp + (b0 + group) * SPstr + nc)     = make_float2(acc[t2][0], acc[t2][1]);
            *(float2*)(sp + (b0 + group + 8) * SPstr + nc) = make_float2(acc[t2][2], acc[t2][3]);
        }
        __syncthreads();

        // nonlinearity: 512 (b,j) items, 2 per thread
#pragma unroll
        for (int u = 0; u < 2; u++) {
            int it = tid + u * 256, b = it >> 3, jj = it & 7;
            float f_ = sp[b * SPstr + jj]      + gxa[u][0];
            float i_ = sp[b * SPstr + 8 + jj]  + gxa[u][1];
            float c_ = sp[b * SPstr + 16 + jj] + gxa[u][2];
            float o_ = sp[b * SPstr + 24 + jj] + gxa[u][3];
            float fg = 1.0f / (1.0f + __expf(-f_));
            float ig = 1.0f / (1.0f + __expf(-i_));
            float ct = tanhf(c_);
            float og = 1.0f / (1.0f + __expf(-o_));
            float hh = og * tanhf((fg + ig) * ct);      // faithful: c_prev unused
            float hi = tf32_rna(hh);
            hnw[(size_t)b * HID + j0 + jj] = make_float2(hi, tf32_rna(hh - hi));
            g_hist[(((size_t)dir * SEQ + s) * BSZ + b) * HID + j0 + jj] = hh;
        }

        // ---- grid barrier (all 128 CTAs resident) ----
        __syncthreads();
        if (tid == 0) {
            __threadfence();
            atomicAdd(&g_cnt[t], 1u);
            while (*(volatile unsigned*)&g_cnt[t] < (unsigned)NCTA) { }
        }
        __syncthreads();
    }
}

// ---------------- kernel 5: pooled = max_s tanh(h_fwd * h_bwd) ----------------
__global__ void k_pool() {
    int b = blockIdx.y;
    int h = blockIdx.x * 128 + threadIdx.x;
    float m = -2.0f;
    const float* pf = g_hist + (size_t)b * HID + h;
    const float* pb = g_hist + (size_t)SEQ * BSZ * HID + (size_t)b * HID + h;
    for (int s = 0; s < SEQ; s++) {
        float a = pf[(size_t)s * BSZ * HID];
        float c = pb[(size_t)s * BSZ * HID];
        m = fmaxf(m, tanhf(a * c));
    }
    g_pooled[b * HID + h] = m;
}

// ---------------- kernel 6: out = pooled @ Wout^T + bout ----------------
__global__ void k_out(const float* __restrict__ Wout, const float* __restrict__ bout,
                      float* __restrict__ out) {
    int b = blockIdx.x;
    int c = threadIdx.x >> 5;
    int lane = threadIdx.x & 31;
    float sum = 0.0f;
    for (int h = lane; h < HID; h += 32)
        sum += g_pooled[b * HID + h] * Wout[c * HID + h];
#pragma unroll
    for (int off = 16; off; off >>= 1)
        sum += __shfl_down_sync(0xffffffffu, sum, off);
    if (lane == 0) out[b * CLS + c] = sum + bout[c];
}

// ---------------- launcher ----------------
extern "C" void kernel_launch(void* const* d_in, const int* in_sizes, int n_in,
                              void* d_out, int out_size) {
    const int*   x     = (const int*)d_in[0];
    const float* embed = (const float*)d_in[1];
    const float* fwdW  = (const float*)d_in[2];
    const float* fwdb  = (const float*)d_in[3];
    const float* bwdW  = (const float*)d_in[4];
    const float* bwdb  = (const float*)d_in[5];
    const float* Wout  = (const float*)d_in[6];
    const float* bout  = (const float*)d_in[7];
    float* out = (float*)d_out;

    cudaFuncSetAttribute(k_gemm_tc,  cudaFuncAttributeMaxDynamicSharedMemorySize, GEMM_SMEM);
    cudaFuncSetAttribute(k_recur_tc, cudaFuncAttributeMaxDynamicSharedMemorySize, RECUR_SMEM);

    k_zero<<<512, 256>>>();
    k_split<<<2 * WELEM / 256, 256>>>(fwdW, bwdW);
    k_gather<<<MROWS, 128>>>(x, embed);
    k_gemm_tc<<<dim3(64, 128), 256, GEMM_SMEM>>>(fwdb, bwdb);
    k_recur_tc<<<NCTA, 256, RECUR_SMEM>>>();
    k_pool<<<dim3(HID / 128, BSZ), 128>>>();
    k_out<<<BSZ, CLS * 32>>>(Wout, bout, out);
}

// round 5
// speedup vs baseline: 1.4896x; 1.4896x over previous
#include <cuda_runtime.h>
#include <cuda_bf16.h>
#include <cstdint>

// ---------------- problem constants ----------------
static const int BSZ   = 64;
static const int SEQ   = 256;
static const int DIM   = 512;
static const int HID   = 512;
static const int DHID  = 1024;
static const int NGATE = 2048;              // 4*HID per direction
static const int MROWS = SEQ * BSZ;         // 16384
static const int NTOT  = 4096;              // both directions' gate cols
static const int CLS   = 5;
static const int NCTA  = 128;               // persistent CTAs (<=148 SMs)

// ---------------- device scratch ----------------
__device__ __nv_bfloat16 g_xbf_hi[(size_t)MROWS * DIM];   // 16 MB
__device__ __nv_bfloat16 g_xbf_lo[(size_t)MROWS * DIM];   // 16 MB
__device__ __nv_bfloat16 g_wbf_hi[(size_t)NTOT * DIM];    // x-part of W, 4 MB
__device__ __nv_bfloat16 g_wbf_lo[(size_t)NTOT * DIM];    // 4 MB
__device__ float  g_gx [2L * SEQ * BSZ * NGATE];          // x-projection + bias
__device__ float  g_hbuf[2 * 2 * BSZ * HID];              // [dir][parity][b][h]
__device__ float  g_hist[2L * SEQ * BSZ * HID];
__device__ float  g_pooled[BSZ * HID];
__device__ unsigned g_cnt[SEQ];

// ---------------- helpers ----------------
__device__ __forceinline__ void ffma2(unsigned long long& d,
                                      unsigned long long a, unsigned long long b) {
    asm volatile("fma.rn.f32x2 %0, %1, %2, %0;" : "+l"(d) : "l"(a), "l"(b));
}
__device__ __forceinline__ uint32_t smem_u32(const void* p) {
    uint32_t a;
    asm("{ .reg .u64 t; cvta.to.shared.u64 t, %1; cvt.u32.u64 %0, t; }" : "=r"(a) : "l"(p));
    return a;
}
#define SWZ128(off) ((off) ^ (((off) >> 3) & 0x70))

__device__ __forceinline__ void ldsm_x4(uint32_t* r, uint32_t addr) {
    asm volatile("ldmatrix.sync.aligned.m8n8.x4.shared.b16 {%0,%1,%2,%3}, [%4];"
                 : "=r"(r[0]), "=r"(r[1]), "=r"(r[2]), "=r"(r[3]) : "r"(addr));
}
// D(16x8 f32) += A(16x16 bf16 row) * B(16x8 bf16 col)
__device__ __forceinline__ void mma16816(float* d, const uint32_t* a,
                                         uint32_t b0, uint32_t b1) {
    asm volatile(
        "mma.sync.aligned.m16n8k16.row.col.f32.bf16.bf16.f32 "
        "{%0,%1,%2,%3},{%4,%5,%6,%7},{%8,%9},{%0,%1,%2,%3};"
        : "+f"(d[0]), "+f"(d[1]), "+f"(d[2]), "+f"(d[3])
        : "r"(a[0]), "r"(a[1]), "r"(a[2]), "r"(a[3]), "r"(b0), "r"(b1));
}

extern __shared__ char dynraw[];

// ---------------- kernel 0: zero h state + barrier counters ----------------
__global__ void k_zero() {
    int i = blockIdx.x * blockDim.x + threadIdx.x;
    if (i < 4 * BSZ * HID) g_hbuf[i] = 0.0f;
    if (i < SEQ) g_cnt[i] = 0u;
}

// ---------------- kernel 1: split W x-part into bf16 hi/lo planes ------------
__global__ void k_splitw(const float* __restrict__ fwdW, const float* __restrict__ bwdW) {
    size_t i = (size_t)blockIdx.x * 256 + threadIdx.x;    // over NTOT*DIM
    int n = (int)(i >> 9), k = (int)(i & 511);
    int dir = n >> 11, ng = n & 2047;
    float w = (dir ? bwdW : fwdW)[(size_t)ng * DHID + k];
    __nv_bfloat16 hi = __float2bfloat16(w);
    g_wbf_hi[i] = hi;
    g_wbf_lo[i] = __float2bfloat16(w - __bfloat162float(hi));
}

// ---------------- kernel 2: embedding gather + bf16 split ----------------
__global__ void k_gather(const int* __restrict__ x, const float* __restrict__ embed) {
    int sb = blockIdx.x;                    // sb = s*BSZ + b
    int b = sb & (BSZ - 1);
    int s = sb >> 6;
    int tok = x[b * SEQ + s];
    int c = threadIdx.x * 4;
    float4 v = *(const float4*)(embed + (size_t)tok * DIM + c);
    size_t base = (size_t)sb * DIM + c;
    float vv[4] = {v.x, v.y, v.z, v.w};
    __nv_bfloat16 h[4], l[4];
#pragma unroll
    for (int q = 0; q < 4; q++) {
        h[q] = __float2bfloat16(vv[q]);
        l[q] = __float2bfloat16(vv[q] - __bfloat162float(h[q]));
    }
    *(__nv_bfloat162*)(g_xbf_hi + base)     = __nv_bfloat162{h[0], h[1]};
    *(__nv_bfloat162*)(g_xbf_hi + base + 2) = __nv_bfloat162{h[2], h[3]};
    *(__nv_bfloat162*)(g_xbf_lo + base)     = __nv_bfloat162{l[0], l[1]};
    *(__nv_bfloat162*)(g_xbf_lo + base + 2) = __nv_bfloat162{l[2], l[3]};
}

// ---------------- kernel 3: x-projection GEMM (bf16 mma + ldmatrix) ----------
// C[m][n] = sum_k xs[m][k]*W[n][k] + bias(n).  Tile M=128, N=128, Kchunk=64.
// 3-pass hi/lo split: D += Ahi*Bhi + Ahi*Blo + Alo*Bhi  (fp32 accumulate).
static const int SM_A_HI = 0;          // 128 rows x 128B (SW128)
static const int SM_A_LO = 16384;
static const int SM_B_HI = 32768;
static const int SM_B_LO = 49152;
static const int GEMM_SMEM = 65536;

__global__ void __launch_bounds__(256, 2)
k_gemm_bf16(const float* __restrict__ fwdb, const float* __restrict__ bwdb) {
    const int tid = threadIdx.x, wid = tid >> 5, lane = tid & 31;
    const int m0 = blockIdx.y * 128;
    const int n0 = blockIdx.x * 128;
    const int dir = n0 >> 11, ngbase = n0 & 2047;
    const uint32_t smem = smem_u32(dynraw);

    const int wm = (wid >> 1) * 32;         // warp tile: 32 m x 64 n
    const int wn = (wid & 1) * 64;

    // ldmatrix lane decode: sel&1 -> +8 rows, sel>>1 -> +8 k (16B chunk)
    const int lm  = lane & 7;
    const int sel = lane >> 3;
    const int rplus = (sel & 1) * 8;
    const int cplus = (sel >> 1) * 16;      // bytes

    const int srow = tid >> 3, sc16 = tid & 7;   // staging decode (1024 chunks/plane)

    float acc[2][8][4];
#pragma unroll
    for (int i = 0; i < 2; i++)
#pragma unroll
        for (int j = 0; j < 8; j++)
#pragma unroll
            for (int r = 0; r < 4; r++) acc[i][j][r] = 0.0f;

    for (int kc = 0; kc < 8; kc++) {
        const int k0 = kc * 64;
        // ---- stage 4 planes, each 128 rows x 128B ----
#pragma unroll
        for (int it = 0; it < 4; it++) {
            int row = srow + it * 32;
            uint32_t off = SWZ128((uint32_t)(row * 128 + sc16 * 16));
            size_t ga = (size_t)(m0 + row) * DIM + k0 + sc16 * 8;
            size_t gb = (size_t)(n0 + row) * DIM + k0 + sc16 * 8;
            *(uint4*)(dynraw + SM_A_HI + off) = *(const uint4*)(g_xbf_hi + ga);
            *(uint4*)(dynraw + SM_A_LO + off) = *(const uint4*)(g_xbf_lo + ga);
            *(uint4*)(dynraw + SM_B_HI + off) = *(const uint4*)(g_wbf_hi + gb);
            *(uint4*)(dynraw + SM_B_LO + off) = *(const uint4*)(g_wbf_lo + gb);
        }
        __syncthreads();

#pragma unroll
        for (int ks = 0; ks < 4; ks++) {
            const int kb = ks * 32;         // byte offset of k16 step within 128B row
            // A fragments: 2 m16 tiles, hi+lo
            uint32_t ahi[2][4], alo[2][4];
#pragma unroll
            for (int i = 0; i < 2; i++) {
                uint32_t off = SWZ128((uint32_t)((wm + i * 16 + lm + rplus) * 128 + kb + cplus));
                ldsm_x4(ahi[i], smem + SM_A_HI + off);
                ldsm_x4(alo[i], smem + SM_A_LO + off);
            }
            // B: 4 n16 tiles; frags n8: {r0,r2} and {r1,r3}
#pragma unroll
            for (int j = 0; j < 4; j++) {
                uint32_t off = SWZ128((uint32_t)((wn + j * 16 + lm + rplus) * 128 + kb + cplus));
                uint32_t bh[4], bl[4];
                ldsm_x4(bh, smem + SM_B_HI + off);
                ldsm_x4(bl, smem + SM_B_LO + off);
#pragma unroll
                for (int i = 0; i < 2; i++) {
                    mma16816(acc[i][j * 2],     ahi[i], bh[0], bh[2]);
                    mma16816(acc[i][j * 2 + 1], ahi[i], bh[1], bh[3]);
                    mma16816(acc[i][j * 2],     ahi[i], bl[0], bl[2]);
                    mma16816(acc[i][j * 2 + 1], ahi[i], bl[1], bl[3]);
                    mma16816(acc[i][j * 2],     alo[i], bh[0], bh[2]);
                    mma16816(acc[i][j * 2 + 1], alo[i], bh[1], bh[3]);
                }
            }
        }
        __syncthreads();
    }

    // ---- epilogue: add bias, write float2 pairs ----
    const float* bv = dir ? bwdb : fwdb;
    const size_t dirbase = (size_t)dir * SEQ * BSZ * NGATE;
#pragma unroll
    for (int i = 0; i < 2; i++) {
        int mr0 = m0 + wm + i * 16 + (lane >> 2);
#pragma unroll
        for (int j = 0; j < 8; j++) {
            int ng = ngbase + wn + j * 8 + 2 * (lane & 3);
            float2 bb = *(const float2*)(bv + ng);
            *(float2*)(g_gx + dirbase + (size_t)mr0 * NGATE + ng) =
                make_float2(acc[i][j][0] + bb.x, acc[i][j][1] + bb.y);
            *(float2*)(g_gx + dirbase + (size_t)(mr0 + 8) * NGATE + ng) =
                make_float2(acc[i][j][2] + bb.x, acc[i][j][3] + bb.y);
        }
    }
}

// ---------------- kernel 4: persistent recurrence (FFMA2, proven) ----------
static const int RECUR_SMEM = (128 * 33 + 2 * 64 * 17) * 16;   // 102400 B

__global__ void __launch_bounds__(256, 1)
k_recur(const float* __restrict__ fwdW, const float* __restrict__ bwdW) {
    float4* dynsm = (float4*)dynraw;
    const int bid = blockIdx.x;
    const int dir = bid >> 6;
    const int j0 = (bid & 63) * 8;
    const float* Wd = dir ? bwdW : fwdW;
    const int tid = threadIdx.x, wid = tid >> 5, lane = tid & 31;
    const int g = lane >> 3, jj = lane & 7;

    float4* w4  = dynsm;                 // [k4][33]
    float4* h4a = dynsm + 128 * 33;      // [b][17]
    float4* h4b = h4a + 64 * 17;

#pragma unroll
    for (int i = 0; i < 16; i++) {
        int idx = i * 256 + tid;
        int c = idx >> 7, k4 = idx & 127;
        int col = (c >> 3) * HID + j0 + (c & 7);
        w4[k4 * 33 + c] = *(const float4*)(Wd + (size_t)col * DHID + DIM + k4 * 4);
    }
    __syncthreads();

    const int sb = tid >> 4;
    const int sk = tid & 15;

    for (int t = 0; t < SEQ; t++) {
        const int s = dir ? (SEQ - 1 - t) : t;
        const float* hprev = g_hbuf + ((size_t)dir * 2 + (t & 1)) * (BSZ * HID);
        float*       hnew  = g_hbuf + ((size_t)dir * 2 + ((t + 1) & 1)) * (BSZ * HID);

        size_t gxbase = ((size_t)dir * SEQ + s) * BSZ * NGATE;
        const int col = g * HID + j0 + jj;
        float gxv[8];
#pragma unroll
        for (int b8 = 0; b8 < 8; b8++)
            gxv[b8] = g_gx[gxbase + (size_t)(wid * 8 + b8) * NGATE + col];

        unsigned long long acc[8];
#pragma unroll
        for (int i = 0; i < 8; i++) acc[i] = 0ull;

        float4 pre[4];
#pragma unroll
        for (int i = 0; i < 4; i++) {
            int b = i * 16 + sb;
            pre[i] = __ldcg((const float4*)(hprev + (size_t)b * HID + sk * 4));
        }
#pragma unroll
        for (int i = 0; i < 4; i++) h4a[(i * 16 + sb) * 17 + sk] = pre[i];
#pragma unroll
        for (int i = 0; i < 4; i++) {
            int b = i * 16 + sb;
            pre[i] = __ldcg((const float4*)(hprev + (size_t)b * HID + 64 + sk * 4));
        }
        __syncthreads();

        float4* cur = h4a;
        float4* nxt = h4b;
        for (int kc = 0; kc < 8; kc++) {
            const int kbase = kc * 16;
#pragma unroll
            for (int k4 = 0; k4 < 16; k4++) {
                ulonglong2 wv = *(const ulonglong2*)&w4[(kbase + k4) * 33 + lane];
#pragma unroll
                for (int b8 = 0; b8 < 8; b8++) {
                    ulonglong2 hv = *(const ulonglong2*)&cur[(wid * 8 + b8) * 17 + k4];
                    ffma2(acc[b8], hv.x, wv.x);
                    ffma2(acc[b8], hv.y, wv.y);
                }
            }
            if (kc < 7) {
#pragma unroll
                for (int i = 0; i < 4; i++) nxt[(i * 16 + sb) * 17 + sk] = pre[i];
                if (kc < 6) {
                    const float* src = hprev + (kc + 2) * 64;
#pragma unroll
                    for (int i = 0; i < 4; i++) {
                        int b = i * 16 + sb;
                        pre[i] = __ldcg((const float4*)(src + (size_t)b * HID + sk * 4));
                    }
                }
            }
            __syncthreads();
            float4* tmp = cur; cur = nxt; nxt = tmp;
        }

#pragma unroll
        for (int b8 = 0; b8 < 8; b8++) {
            int b = wid * 8 + b8;
            float2 p = *(float2*)&acc[b8];
            float val = p.x + p.y + gxv[b8];
            float gf = __shfl_sync(0xffffffffu, val, jj);
            float gi = __shfl_sync(0xffffffffu, val, 8 + jj);
            float gc = __shfl_sync(0xffffffffu, val, 16 + jj);
            float go = __shfl_sync(0xffffffffu, val, 24 + jj);
            if (g == 0) {
                float f  = 1.0f / (1.0f + __expf(-gf));
                float ii = 1.0f / (1.0f + __expf(-gi));
                float ct = tanhf(gc);
                float oo = 1.0f / (1.0f + __expf(-go));
                float hh = oo * tanhf((f + ii) * ct);
                hnew[(size_t)b * HID + j0 + jj] = hh;
                g_hist[(((size_t)dir * SEQ + s) * BSZ + b) * HID + j0 + jj] = hh;
            }
        }

        __syncthreads();
        if (tid == 0) {
            __threadfence();
            atomicAdd(&g_cnt[t], 1u);
            while (*(volatile unsigned*)&g_cnt[t] < (unsigned)NCTA) { }
        }
        __syncthreads();
    }
}

// ---------------- kernel 5: pooled = max_s tanh(h_fwd * h_bwd) ----------------
__global__ void k_pool() {
    int b = blockIdx.y;
    int h = blockIdx.x * 128 + threadIdx.x;
    float m = -2.0f;
    const float* pf = g_hist + (size_t)b * HID + h;
    const float* pb = g_hist + (size_t)SEQ * BSZ * HID + (size_t)b * HID + h;
    for (int s = 0; s < SEQ; s++) {
        float a = pf[(size_t)s * BSZ * HID];
        float c = pb[(size_t)s * BSZ * HID];
        m = fmaxf(m, tanhf(a * c));
    }
    g_pooled[b * HID + h] = m;
}

// ---------------- kernel 6: out = pooled @ Wout^T + bout ----------------
__global__ void k_out(const float* __restrict__ Wout, const float* __restrict__ bout,
                      float* __restrict__ out) {
    int b = blockIdx.x;
    int c = threadIdx.x >> 5;
    int lane = threadIdx.x & 31;
    float sum = 0.0f;
    for (int h = lane; h < HID; h += 32)
        sum += g_pooled[b * HID + h] * Wout[c * HID + h];
#pragma unroll
    for (int off = 16; off; off >>= 1)
        sum += __shfl_down_sync(0xffffffffu, sum, off);
    if (lane == 0) out[b * CLS + c] = sum + bout[c];
}

// ---------------- launcher ----------------
extern "C" void kernel_launch(void* const* d_in, const int* in_sizes, int n_in,
                              void* d_out, int out_size) {
    const int*   x     = (const int*)d_in[0];
    const float* embed = (const float*)d_in[1];
    const float* fwdW  = (const float*)d_in[2];
    const float* fwdb  = (const float*)d_in[3];
    const float* bwdW  = (const float*)d_in[4];
    const float* bwdb  = (const float*)d_in[5];
    const float* Wout  = (const float*)d_in[6];
    const float* bout  = (const float*)d_in[7];
    float* out = (float*)d_out;

    cudaFuncSetAttribute(k_gemm_bf16, cudaFuncAttributeMaxDynamicSharedMemorySize, GEMM_SMEM);
    cudaFuncSetAttribute(k_recur,     cudaFuncAttributeMaxDynamicSharedMemorySize, RECUR_SMEM);

    k_zero<<<512, 256>>>();
    k_splitw<<<NTOT * DIM / 256, 256>>>(fwdW, bwdW);
    k_gather<<<MROWS, 128>>>(x, embed);
    k_gemm_bf16<<<dim3(NTOT / 128, MROWS / 128), 256, GEMM_SMEM>>>(fwdb, bwdb);
    k_recur<<<NCTA, 256, RECUR_SMEM>>>(fwdW, bwdW);
    k_pool<<<dim3(HID / 128, BSZ), 128>>>();
    k_out<<<BSZ, CLS * 32>>>(Wout, bout, out);
}

// round 6
// speedup vs baseline: 2.8564x; 1.9176x over previous
#include <cuda_runtime.h>
#include <cuda_bf16.h>
#include <cstdint>

// ---------------- problem constants ----------------
static const int BSZ   = 64;
static const int SEQ   = 256;
static const int DIM   = 512;
static const int HID   = 512;
static const int DHID  = 1024;
static const int NGATE = 2048;              // 4*HID per direction
static const int MROWS = SEQ * BSZ;         // 16384
static const int NTOT  = 4096;              // both directions' gate cols
static const int CLS   = 5;
static const int NCTA  = 128;               // persistent CTAs (<=148 SMs)

// ---------------- device scratch ----------------
__device__ __nv_bfloat16 g_xbf_hi[(size_t)MROWS * DIM];   // 16 MB
__device__ __nv_bfloat16 g_xbf_lo[(size_t)MROWS * DIM];   // 16 MB
__device__ __nv_bfloat16 g_wbf_hi[(size_t)NTOT * DHID];   // full W split, 8 MB
__device__ __nv_bfloat16 g_wbf_lo[(size_t)NTOT * DHID];   // 8 MB
__device__ float  g_gx [2L * SEQ * BSZ * NGATE];          // x-projection + bias
__device__ __nv_bfloat16 g_hbf_hi[2 * 2 * BSZ * HID];     // [dir][parity][b][k]
__device__ __nv_bfloat16 g_hbf_lo[2 * 2 * BSZ * HID];
__device__ float  g_hist[2L * SEQ * BSZ * HID];
__device__ float  g_pooled[BSZ * HID];
__device__ unsigned g_cnt[SEQ];

// ---------------- helpers ----------------
__device__ __forceinline__ uint32_t smem_u32(const void* p) {
    uint32_t a;
    asm("{ .reg .u64 t; cvta.to.shared.u64 t, %1; cvt.u32.u64 %0, t; }" : "=r"(a) : "l"(p));
    return a;
}
#define SWZ128(off) ((off) ^ (((off) >> 3) & 0x70))

__device__ __forceinline__ void ldsm_x4(uint32_t* r, uint32_t addr) {
    asm volatile("ldmatrix.sync.aligned.m8n8.x4.shared.b16 {%0,%1,%2,%3}, [%4];"
                 : "=r"(r[0]), "=r"(r[1]), "=r"(r[2]), "=r"(r[3]) : "r"(addr));
}
// D(16x8 f32) += A(16x16 bf16 row) * B(16x8 bf16 col)
__device__ __forceinline__ void mma16816(float* d, const uint32_t* a,
                                         uint32_t b0, uint32_t b1) {
    asm volatile(
        "mma.sync.aligned.m16n8k16.row.col.f32.bf16.bf16.f32 "
        "{%0,%1,%2,%3},{%4,%5,%6,%7},{%8,%9},{%0,%1,%2,%3};"
        : "+f"(d[0]), "+f"(d[1]), "+f"(d[2]), "+f"(d[3])
        : "r"(a[0]), "r"(a[1]), "r"(a[2]), "r"(a[3]), "r"(b0), "r"(b1));
}

extern __shared__ char dynraw[];

// ---------------- kernel 0: zero h planes + barrier counters ----------------
__global__ void k_zero() {
    int i = blockIdx.x * blockDim.x + threadIdx.x;
    if (i < 2 * 2 * BSZ * HID) {
        g_hbf_hi[i] = __float2bfloat16(0.0f);
        g_hbf_lo[i] = __float2bfloat16(0.0f);
    }
    if (i < SEQ) g_cnt[i] = 0u;
}

// ---------------- kernel 1: split full W into bf16 hi/lo planes ------------
__global__ void k_splitw(const float* __restrict__ fwdW, const float* __restrict__ bwdW) {
    size_t i = (size_t)blockIdx.x * 256 + threadIdx.x;    // over NTOT*DHID
    int n = (int)(i >> 10), k = (int)(i & 1023);
    int dir = n >> 11, ng = n & 2047;
    float w = (dir ? bwdW : fwdW)[(size_t)ng * DHID + k];
    __nv_bfloat16 hi = __float2bfloat16(w);
    g_wbf_hi[i] = hi;
    g_wbf_lo[i] = __float2bfloat16(w - __bfloat162float(hi));
}

// ---------------- kernel 2: embedding gather + bf16 split ----------------
__global__ void k_gather(const int* __restrict__ x, const float* __restrict__ embed) {
    int sb = blockIdx.x;                    // sb = s*BSZ + b
    int b = sb & (BSZ - 1);
    int s = sb >> 6;
    int tok = x[b * SEQ + s];
    int c = threadIdx.x * 4;
    float4 v = *(const float4*)(embed + (size_t)tok * DIM + c);
    size_t base = (size_t)sb * DIM + c;
    float vv[4] = {v.x, v.y, v.z, v.w};
    __nv_bfloat16 h[4], l[4];
#pragma unroll
    for (int q = 0; q < 4; q++) {
        h[q] = __float2bfloat16(vv[q]);
        l[q] = __float2bfloat16(vv[q] - __bfloat162float(h[q]));
    }
    *(__nv_bfloat162*)(g_xbf_hi + base)     = __nv_bfloat162{h[0], h[1]};
    *(__nv_bfloat162*)(g_xbf_hi + base + 2) = __nv_bfloat162{h[2], h[3]};
    *(__nv_bfloat162*)(g_xbf_lo + base)     = __nv_bfloat162{l[0], l[1]};
    *(__nv_bfloat162*)(g_xbf_lo + base + 2) = __nv_bfloat162{l[2], l[3]};
}

// ---------------- kernel 3: x-projection GEMM (bf16 mma + ldmatrix) ----------
// C[m][n] = sum_k xs[m][k]*W[n][k] + bias(n).  Tile M=128, N=128, Kchunk=64.
static const int SM_A_HI = 0;          // 128 rows x 128B (SW128)
static const int SM_A_LO = 16384;
static const int SM_B_HI = 32768;
static const int SM_B_LO = 49152;
static const int GEMM_SMEM = 65536;

__global__ void __launch_bounds__(256, 2)
k_gemm_bf16(const float* __restrict__ fwdb, const float* __restrict__ bwdb) {
    const int tid = threadIdx.x, wid = tid >> 5, lane = tid & 31;
    const int m0 = blockIdx.y * 128;
    const int n0 = blockIdx.x * 128;
    const int dir = n0 >> 11, ngbase = n0 & 2047;
    const uint32_t smem = smem_u32(dynraw);

    const int wm = (wid >> 1) * 32;         // warp tile: 32 m x 64 n
    const int wn = (wid & 1) * 64;

    const int lm  = lane & 7;
    const int sel = lane >> 3;
    const int rplus = (sel & 1) * 8;
    const int cplus = (sel >> 1) * 16;      // bytes

    const int srow = tid >> 3, sc16 = tid & 7;

    float acc[2][8][4];
#pragma unroll
    for (int i = 0; i < 2; i++)
#pragma unroll
        for (int j = 0; j < 8; j++)
#pragma unroll
            for (int r = 0; r < 4; r++) acc[i][j][r] = 0.0f;

    for (int kc = 0; kc < 8; kc++) {
        const int k0 = kc * 64;
#pragma unroll
        for (int it = 0; it < 4; it++) {
            int row = srow + it * 32;
            uint32_t off = SWZ128((uint32_t)(row * 128 + sc16 * 16));
            size_t ga = (size_t)(m0 + row) * DIM + k0 + sc16 * 8;
            size_t gb = (size_t)(n0 + row) * DHID + k0 + sc16 * 8;
            *(uint4*)(dynraw + SM_A_HI + off) = *(const uint4*)(g_xbf_hi + ga);
            *(uint4*)(dynraw + SM_A_LO + off) = *(const uint4*)(g_xbf_lo + ga);
            *(uint4*)(dynraw + SM_B_HI + off) = *(const uint4*)(g_wbf_hi + gb);
            *(uint4*)(dynraw + SM_B_LO + off) = *(const uint4*)(g_wbf_lo + gb);
        }
        __syncthreads();

#pragma unroll
        for (int ks = 0; ks < 4; ks++) {
            const int kb = ks * 32;
            uint32_t ahi[2][4], alo[2][4];
#pragma unroll
            for (int i = 0; i < 2; i++) {
                uint32_t off = SWZ128((uint32_t)((wm + i * 16 + lm + rplus) * 128 + kb + cplus));
                ldsm_x4(ahi[i], smem + SM_A_HI + off);
                ldsm_x4(alo[i], smem + SM_A_LO + off);
            }
#pragma unroll
            for (int j = 0; j < 4; j++) {
                uint32_t off = SWZ128((uint32_t)((wn + j * 16 + lm + rplus) * 128 + kb + cplus));
                uint32_t bh[4], bl[4];
                ldsm_x4(bh, smem + SM_B_HI + off);
                ldsm_x4(bl, smem + SM_B_LO + off);
#pragma unroll
                for (int i = 0; i < 2; i++) {
                    mma16816(acc[i][j * 2],     ahi[i], bh[0], bh[2]);
                    mma16816(acc[i][j * 2 + 1], ahi[i], bh[1], bh[3]);
                    mma16816(acc[i][j * 2],     ahi[i], bl[0], bl[2]);
                    mma16816(acc[i][j * 2 + 1], ahi[i], bl[1], bl[3]);
                    mma16816(acc[i][j * 2],     alo[i], bh[0], bh[2]);
                    mma16816(acc[i][j * 2 + 1], alo[i], bh[1], bh[3]);
                }
            }
        }
        __syncthreads();
    }

    const float* bv = dir ? bwdb : fwdb;
    const size_t dirbase = (size_t)dir * SEQ * BSZ * NGATE;
#pragma unroll
    for (int i = 0; i < 2; i++) {
        int mr0 = m0 + wm + i * 16 + (lane >> 2);
#pragma unroll
        for (int j = 0; j < 8; j++) {
            int ng = ngbase + wn + j * 8 + 2 * (lane & 3);
            float2 bb = *(const float2*)(bv + ng);
            *(float2*)(g_gx + dirbase + (size_t)mr0 * NGATE + ng) =
                make_float2(acc[i][j][0] + bb.x, acc[i][j][1] + bb.y);
            *(float2*)(g_gx + dirbase + (size_t)(mr0 + 8) * NGATE + ng) =
                make_float2(acc[i][j][2] + bb.x, acc[i][j][3] + bb.y);
        }
    }
}

// ---------------- kernel 4: persistent recurrence (bf16 mma + ldmatrix) -----
// 128 CTAs: dir = bid>>6, j0 = (bid&63)*8 -> 32 gate cols x 64 batch, K=512.
// Wh slice resident in smem (hi/lo); h staged from global bf16 planes per step.
static const int RW_HI = 0;              // 8 kc x 32 rows x 128B = 32 KB
static const int RW_LO = 32768;
static const int RH_HI = 65536;          // 8 kc x 64 rows x 128B = 64 KB
static const int RH_LO = 131072;
static const int RSP   = 196608;         // 64 x 34 floats exchange
static const int RECUR_SMEM = RSP + BSZ * 34 * 4;   // 205312 B

__global__ void __launch_bounds__(256, 1)
k_recur_mma() {
    const int bid = blockIdx.x;
    const int dir = bid >> 6;
    const int j0 = (bid & 63) * 8;
    const int tid = threadIdx.x, wid = tid >> 5, lane = tid & 31;
    const uint32_t smem = smem_u32(dynraw);

    const int lm  = lane & 7;
    const int sel = lane >> 3;
    const int rplus = (sel & 1) * 8;
    const int cplus = (sel >> 1) * 16;
    const int wm = (wid >> 1) * 16;          // batch tile base (4 m16 tiles)
    const int wn = (wid & 1) * 16;           // col tile base (2 n16 halves)
    float* sp = (float*)(dynraw + RSP);

    // ---- preload Wh slice (k in [512,1024)) hi/lo, SW128 per 64-k chunk ----
#pragma unroll
    for (int it = 0; it < 8; it++) {
        int idx = it * 256 + tid;            // 2048 chunks per plane
        int c = idx >> 6, c16 = idx & 63;    // c: col 0..31; c16: 16B chunk
        int kc = c16 >> 3;
        int n = dir * 2048 + (c >> 3) * HID + j0 + (c & 7);
        uint32_t off = (uint32_t)(kc * 4096 + SWZ128(c * 128 + (c16 & 7) * 16));
        size_t src = (size_t)n * DHID + 512 + c16 * 8;
        *(uint4*)(dynraw + RW_HI + off) = *(const uint4*)(g_wbf_hi + src);
        *(uint4*)(dynraw + RW_LO + off) = *(const uint4*)(g_wbf_lo + src);
    }
    __syncthreads();

    for (int t = 0; t < SEQ; t++) {
        const int s = dir ? (SEQ - 1 - t) : t;
        const __nv_bfloat16* hp_hi = g_hbf_hi + ((size_t)dir * 2 + (t & 1)) * (BSZ * HID);
        const __nv_bfloat16* hp_lo = g_hbf_lo + ((size_t)dir * 2 + (t & 1)) * (BSZ * HID);
        __nv_bfloat16* hn_hi = g_hbf_hi + ((size_t)dir * 2 + ((t + 1) & 1)) * (BSZ * HID);
        __nv_bfloat16* hn_lo = g_hbf_lo + ((size_t)dir * 2 + ((t + 1) & 1)) * (BSZ * HID);

        // prefetch x-projections for the nonlinearity pass
        size_t gxbase = ((size_t)dir * SEQ + s) * BSZ * NGATE;
        float gxa[2][4];
#pragma unroll
        for (int u = 0; u < 2; u++) {
            int it = tid + u * 256, b = it >> 3, jj = it & 7;
#pragma unroll
            for (int g = 0; g < 4; g++)
                gxa[u][g] = g_gx[gxbase + (size_t)b * NGATE + g * HID + j0 + jj];
        }

        // ---- stage h (both planes) into smem; L2-only loads (L1 stale) ----
#pragma unroll
        for (int it = 0; it < 16; it++) {
            int idx = it * 256 + tid;        // 4096 chunks per plane
            int b = idx >> 6, c16 = idx & 63;
            int kc = c16 >> 3;
            uint32_t off = (uint32_t)(kc * 8192 + SWZ128(b * 128 + (c16 & 7) * 16));
            size_t src = (size_t)b * HID + c16 * 8;
            *(uint4*)(dynraw + RH_HI + off) = __ldcg((const uint4*)(hp_hi + src));
            *(uint4*)(dynraw + RH_LO + off) = __ldcg((const uint4*)(hp_lo + src));
        }
        __syncthreads();

        float acc[2][4];
#pragma unroll
        for (int j = 0; j < 2; j++)
#pragma unroll
            for (int r = 0; r < 4; r++) acc[j][r] = 0.0f;

#pragma unroll 2
        for (int kc = 0; kc < 8; kc++) {
#pragma unroll
            for (int ks = 0; ks < 4; ks++) {
                const int kb = ks * 32;
                uint32_t ah[4], al[4], bh[4], bl[4];
                uint32_t aoff = (uint32_t)(kc * 8192 + SWZ128((wm + lm + rplus) * 128 + kb + cplus));
                ldsm_x4(ah, smem + RH_HI + aoff);
                ldsm_x4(al, smem + RH_LO + aoff);
                uint32_t boff = (uint32_t)(kc * 4096 + SWZ128((wn + lm + rplus) * 128 + kb + cplus));
                ldsm_x4(bh, smem + RW_HI + boff);
                ldsm_x4(bl, smem + RW_LO + boff);
                mma16816(acc[0], ah, bh[0], bh[2]);
                mma16816(acc[1], ah, bh[1], bh[3]);
                mma16816(acc[0], ah, bl[0], bl[2]);
                mma16816(acc[1], ah, bl[1], bl[3]);
                mma16816(acc[0], al, bh[0], bh[2]);
                mma16816(acc[1], al, bh[1], bh[3]);
            }
        }

        // ---- exchange preacts via smem ----
#pragma unroll
        for (int j = 0; j < 2; j++) {
            int c = wn + j * 8 + 2 * (lane & 3);
            int b = wm + (lane >> 2);
            *(float2*)(sp + b * 34 + c)       = make_float2(acc[j][0], acc[j][1]);
            *(float2*)(sp + (b + 8) * 34 + c) = make_float2(acc[j][2], acc[j][3]);
        }
        __syncthreads();

        // ---- nonlinearity: 512 (b,jj) items, 2 per thread ----
#pragma unroll
        for (int u = 0; u < 2; u++) {
            int it = tid + u * 256, b = it >> 3, jj = it & 7;
            float f_ = sp[b * 34 + jj]      + gxa[u][0];
            float i_ = sp[b * 34 + 8 + jj]  + gxa[u][1];
            float c_ = sp[b * 34 + 16 + jj] + gxa[u][2];
            float o_ = sp[b * 34 + 24 + jj] + gxa[u][3];
            float fg = 1.0f / (1.0f + __expf(-f_));
            float ig = 1.0f / (1.0f + __expf(-i_));
            float ct = tanhf(c_);
            float og = 1.0f / (1.0f + __expf(-o_));
            float hh = og * tanhf((fg + ig) * ct);      // faithful: c_prev unused
            int j = j0 + jj;
            g_hist[(((size_t)dir * SEQ + s) * BSZ + b) * HID + j] = hh;
            __nv_bfloat16 hi = __float2bfloat16(hh);
            hn_hi[(size_t)b * HID + j] = hi;
            hn_lo[(size_t)b * HID + j] = __float2bfloat16(hh - __bfloat162float(hi));
        }

        // ---- grid barrier (all 128 CTAs resident) ----
        __syncthreads();
        if (tid == 0) {
            __threadfence();
            atomicAdd(&g_cnt[t], 1u);
            while (*(volatile unsigned*)&g_cnt[t] < (unsigned)NCTA) { }
        }
        __syncthreads();
    }
}

// ---------------- kernel 5: pooled = max_s tanh(h_fwd * h_bwd) ----------------
__global__ void k_pool() {
    int b = blockIdx.y;
    int h = blockIdx.x * 128 + threadIdx.x;
    float m = -2.0f;
    const float* pf = g_hist + (size_t)b * HID + h;
    const float* pb = g_hist + (size_t)SEQ * BSZ * HID + (size_t)b * HID + h;
    for (int s = 0; s < SEQ; s++) {
        float a = pf[(size_t)s * BSZ * HID];
        float c = pb[(size_t)s * BSZ * HID];
        m = fmaxf(m, tanhf(a * c));
    }
    g_pooled[b * HID + h] = m;
}

// ---------------- kernel 6: out = pooled @ Wout^T + bout ----------------
__global__ void k_out(const float* __restrict__ Wout, const float* __restrict__ bout,
                      float* __restrict__ out) {
    int b = blockIdx.x;
    int c = threadIdx.x >> 5;
    int lane = threadIdx.x & 31;
    float sum = 0.0f;
    for (int h = lane; h < HID; h += 32)
        sum += g_pooled[b * HID + h] * Wout[c * HID + h];
#pragma unroll
    for (int off = 16; off; off >>= 1)
        sum += __shfl_down_sync(0xffffffffu, sum, off);
    if (lane == 0) out[b * CLS + c] = sum + bout[c];
}

// ---------------- launcher ----------------
extern "C" void kernel_launch(void* const* d_in, const int* in_sizes, int n_in,
                              void* d_out, int out_size) {
    const int*   x     = (const int*)d_in[0];
    const float* embed = (const float*)d_in[1];
    const float* fwdW  = (const float*)d_in[2];
    const float* fwdb  = (const float*)d_in[3];
    const float* bwdW  = (const float*)d_in[4];
    const float* bwdb  = (const float*)d_in[5];
    const float* Wout  = (const float*)d_in[6];
    const float* bout  = (const float*)d_in[7];
    float* out = (float*)d_out;

    cudaFuncSetAttribute(k_gemm_bf16, cudaFuncAttributeMaxDynamicSharedMemorySize, GEMM_SMEM);
    cudaFuncSetAttribute(k_recur_mma, cudaFuncAttributeMaxDynamicSharedMemorySize, RECUR_SMEM);

    k_zero<<<512, 256>>>();
    k_splitw<<<NTOT * DHID / 256, 256>>>(fwdW, bwdW);
    k_gather<<<MROWS, 128>>>(x, embed);
    k_gemm_bf16<<<dim3(NTOT / 128, MROWS / 128), 256, GEMM_SMEM>>>(fwdb, bwdb);
    k_recur_mma<<<NCTA, 256, RECUR_SMEM>>>();
    k_pool<<<dim3(HID / 128, BSZ), 128>>>();
    k_out<<<BSZ, CLS * 32>>>(Wout, bout, out);
}

// round 9
// speedup vs baseline: 3.2762x; 1.1470x over previous
#include <cuda_runtime.h>
#include <cuda_fp16.h>
#include <cstdint>

// ---------------- problem constants ----------------
static const int BSZ   = 64;
static const int SEQ   = 256;
static const int DIM   = 512;
static const int HID   = 512;
static const int DHID  = 1024;
static const int NGATE = 2048;              // 4*HID per direction
static const int MROWS = SEQ * BSZ;         // 16384
static const int NTOT  = 4096;              // both directions' gate cols
static const int CLS   = 5;
static const int NCTA  = 128;               // persistent CTAs (<=148 SMs)

// ---------------- device scratch ----------------
__device__ __half g_xh_hi[(size_t)MROWS * DIM];    // 16 MB
__device__ __half g_xh_lo[(size_t)MROWS * DIM];    // 16 MB
__device__ __half g_wh   [(size_t)NTOT * DHID];    // W single fp16 plane, 8 MB
__device__ float  g_gx [2L * SEQ * BSZ * NGATE];   // x-projection + bias
__device__ __half g_hh_hi[2 * 2 * BSZ * HID];      // [dir][parity][b][k]
__device__ __half g_hh_lo[2 * 2 * BSZ * HID];
__device__ float  g_hist[2L * SEQ * BSZ * HID];
__device__ float  g_pooled[BSZ * HID];
__device__ unsigned g_cnt[SEQ];

// ---------------- helpers ----------------
__device__ __forceinline__ uint32_t smem_u32(const void* p) {
    uint32_t a;
    asm("{ .reg .u64 t; cvta.to.shared.u64 t, %1; cvt.u32.u64 %0, t; }" : "=r"(a) : "l"(p));
    return a;
}
#define SWZ128(off) ((off) ^ (((off) >> 3) & 0x70))

__device__ __forceinline__ void ldsm_x4(uint32_t* r, uint32_t addr) {
    asm volatile("ldmatrix.sync.aligned.m8n8.x4.shared.b16 {%0,%1,%2,%3}, [%4];"
                 : "=r"(r[0]), "=r"(r[1]), "=r"(r[2]), "=r"(r[3]) : "r"(addr));
}
// D(16x8 f32) += A(16x16 f16 row) * B(16x8 f16 col)
__device__ __forceinline__ void mma16816(float* d, const uint32_t* a,
                                         uint32_t b0, uint32_t b1) {
    asm volatile(
        "mma.sync.aligned.m16n8k16.row.col.f32.f16.f16.f32 "
        "{%0,%1,%2,%3},{%4,%5,%6,%7},{%8,%9},{%0,%1,%2,%3};"
        : "+f"(d[0]), "+f"(d[1]), "+f"(d[2]), "+f"(d[3])
        : "r"(a[0]), "r"(a[1]), "r"(a[2]), "r"(a[3]), "r"(b0), "r"(b1));
}

extern __shared__ char dynraw[];

// ---------------- kernel 0: zero h planes + barrier counters ----------------
__global__ void k_zero() {
    int i = blockIdx.x * blockDim.x + threadIdx.x;
    if (i < 2 * 2 * BSZ * HID) {
        g_hh_hi[i] = __float2half(0.0f);
        g_hh_lo[i] = __float2half(0.0f);
    }
    if (i < SEQ) g_cnt[i] = 0u;
}

// ---------------- kernel 1: W -> single fp16 plane --------------------------
__global__ void k_splitw(const float* __restrict__ fwdW, const float* __restrict__ bwdW) {
    size_t i = (size_t)blockIdx.x * 256 + threadIdx.x;    // over NTOT*DHID
    int n = (int)(i >> 10), k = (int)(i & 1023);
    int dir = n >> 11, ng = n & 2047;
    float w = (dir ? bwdW : fwdW)[(size_t)ng * DHID + k];
    g_wh[i] = __float2half(w);
}

// ---------------- kernel 2: embedding gather + fp16 hi/lo split --------------
__global__ void k_gather(const int* __restrict__ x, const float* __restrict__ embed) {
    int sb = blockIdx.x;                    // sb = s*BSZ + b
    int b = sb & (BSZ - 1);
    int s = sb >> 6;
    int tok = x[b * SEQ + s];
    int c = threadIdx.x * 4;
    float4 v = *(const float4*)(embed + (size_t)tok * DIM + c);
    size_t base = (size_t)sb * DIM + c;
    float vv[4] = {v.x, v.y, v.z, v.w};
    __half h[4], l[4];
#pragma unroll
    for (int q = 0; q < 4; q++) {
        h[q] = __float2half(vv[q]);
        l[q] = __float2half(vv[q] - __half2float(h[q]));
    }
    *(__half2*)(g_xh_hi + base)     = __half2{h[0], h[1]};
    *(__half2*)(g_xh_hi + base + 2) = __half2{h[2], h[3]};
    *(__half2*)(g_xh_lo + base)     = __half2{l[0], l[1]};
    *(__half2*)(g_xh_lo + base + 2) = __half2{l[2], l[3]};
}

// ---------------- kernel 3: x-projection GEMM (fp16 mma, 2-pass) -------------
// C[m][n] = sum_k xs[m][k]*W[n][k] + bias(n).  Tile M=128, N=128, Kchunk=64.
static const int SM_A_HI = 0;          // 128 rows x 128B (SW128)
static const int SM_A_LO = 16384;
static const int SM_B    = 32768;
static const int GEMM_SMEM = 49152;

__global__ void __launch_bounds__(256, 2)
k_gemm_fp16(const float* __restrict__ fwdb, const float* __restrict__ bwdb) {
    const int tid = threadIdx.x, wid = tid >> 5, lane = tid & 31;
    const int m0 = blockIdx.y * 128;
    const int n0 = blockIdx.x * 128;
    const int dir = n0 >> 11, ngbase = n0 & 2047;
    const uint32_t smem = smem_u32(dynraw);

    const int wm = (wid >> 1) * 32;         // warp tile: 32 m x 64 n
    const int wn = (wid & 1) * 64;

    const int lm  = lane & 7;
    const int sel = lane >> 3;
    const int rplus = (sel & 1) * 8;
    const int cplus = (sel >> 1) * 16;      // bytes

    const int srow = tid >> 3, sc16 = tid & 7;

    float acc[2][8][4];
#pragma unroll
    for (int i = 0; i < 2; i++)
#pragma unroll
        for (int j = 0; j < 8; j++)
#pragma unroll
            for (int r = 0; r < 4; r++) acc[i][j][r] = 0.0f;

    for (int kc = 0; kc < 8; kc++) {
        const int k0 = kc * 64;
#pragma unroll
        for (int it = 0; it < 4; it++) {
            int row = srow + it * 32;
            uint32_t off = SWZ128((uint32_t)(row * 128 + sc16 * 16));
            size_t ga = (size_t)(m0 + row) * DIM + k0 + sc16 * 8;
            size_t gb = (size_t)(n0 + row) * DHID + k0 + sc16 * 8;
            *(uint4*)(dynraw + SM_A_HI + off) = *(const uint4*)(g_xh_hi + ga);
            *(uint4*)(dynraw + SM_A_LO + off) = *(const uint4*)(g_xh_lo + ga);
            *(uint4*)(dynraw + SM_B + off)    = *(const uint4*)(g_wh + gb);
        }
        __syncthreads();

#pragma unroll
        for (int ks = 0; ks < 4; ks++) {
            const int kb = ks * 32;
            uint32_t ahi[2][4], alo[2][4];
#pragma unroll
            for (int i = 0; i < 2; i++) {
                uint32_t off = SWZ128((uint32_t)((wm + i * 16 + lm + rplus) * 128 + kb + cplus));
                ldsm_x4(ahi[i], smem + SM_A_HI + off);
                ldsm_x4(alo[i], smem + SM_A_LO + off);
            }
#pragma unroll
            for (int j = 0; j < 4; j++) {
                uint32_t off = SWZ128((uint32_t)((wn + j * 16 + lm + rplus) * 128 + kb + cplus));
                uint32_t bh[4];
                ldsm_x4(bh, smem + SM_B + off);
#pragma unroll
                for (int i = 0; i < 2; i++) {
                    mma16816(acc[i][j * 2],     ahi[i], bh[0], bh[2]);
                    mma16816(acc[i][j * 2 + 1], ahi[i], bh[1], bh[3]);
                    mma16816(acc[i][j * 2],     alo[i], bh[0], bh[2]);
                    mma16816(acc[i][j * 2 + 1], alo[i], bh[1], bh[3]);
                }
            }
        }
        __syncthreads();
    }

    const float* bv = dir ? bwdb : fwdb;
    const size_t dirbase = (size_t)dir * SEQ * BSZ * NGATE;
#pragma unroll
    for (int i = 0; i < 2; i++) {
        int mr0 = m0 + wm + i * 16 + (lane >> 2);
#pragma unroll
        for (int j = 0; j < 8; j++) {
            int ng = ngbase + wn + j * 8 + 2 * (lane & 3);
            float2 bb = *(const float2*)(bv + ng);
            *(float2*)(g_gx + dirbase + (size_t)mr0 * NGATE + ng) =
                make_float2(acc[i][j][0] + bb.x, acc[i][j][1] + bb.y);
            *(float2*)(g_gx + dirbase + (size_t)(mr0 + 8) * NGATE + ng) =
                make_float2(acc[i][j][2] + bb.x, acc[i][j][3] + bb.y);
        }
    }
}

// ---------------- kernel 4: persistent recurrence (fp16 mma, pipelined) -----
// 128 CTAs: dir = bid>>6, j0 = (bid&63)*8 -> 32 gate cols x 64 batch, K=512.
// W slice resident (single plane); h staged per 64-k chunk, double-buffered.
static const int RW  = 0;               // 8 kc x 32 rows x 128B = 32 KB
static const int RH  = 32768;           // 2 bufs x (2 planes x 64 x 128B) = 32 KB
static const int RSP = 65536;           // 64 x 34 floats exchange
static const int RECUR_SMEM = RSP + BSZ * 34 * 4;   // 74240 B

__global__ void __launch_bounds__(256, 1)
k_recur_mma() {
    const int bid = blockIdx.x;
    const int dir = bid >> 6;
    const int j0 = (bid & 63) * 8;
    const int tid = threadIdx.x, wid = tid >> 5, lane = tid & 31;
    const uint32_t smem = smem_u32(dynraw);

    const int lm  = lane & 7;
    const int sel = lane >> 3;
    const int rplus = (sel & 1) * 8;
    const int cplus = (sel >> 1) * 16;
    const int wm = (wid >> 1) * 16;          // batch tile base (4 m16 tiles)
    const int wn = (wid & 1) * 16;           // col tile base (2 n16 halves)
    float* sp = (float*)(dynraw + RSP);

    // staging decode: thread -> (b, two 16B chunks)
    const int stb = tid >> 2;                // 0..63
    const int stq = (tid & 3) * 2;           // 0,2,4,6

    // ---- preload W slice (k in [512,1024)) single plane, SW128 per chunk ----
#pragma unroll
    for (int it = 0; it < 8; it++) {
        int idx = it * 256 + tid;            // 2048 chunks
        int c = idx >> 6, c16 = idx & 63;
        int kc = c16 >> 3;
        int n = dir * 2048 + (c >> 3) * HID + j0 + (c & 7);
        uint32_t off = (uint32_t)(kc * 4096 + SWZ128(c * 128 + (c16 & 7) * 16));
        *(uint4*)(dynraw + RW + off) = *(const uint4*)(g_wh + (size_t)n * DHID + 512 + c16 * 8);
    }
    __syncthreads();

    for (int t = 0; t < SEQ; t++) {
        const int s = dir ? (SEQ - 1 - t) : t;
        const __half* hp_hi = g_hh_hi + ((size_t)dir * 2 + (t & 1)) * (BSZ * HID);
        const __half* hp_lo = g_hh_lo + ((size_t)dir * 2 + (t & 1)) * (BSZ * HID);
        __half* hn_hi = g_hh_hi + ((size_t)dir * 2 + ((t + 1) & 1)) * (BSZ * HID);
        __half* hn_lo = g_hh_lo + ((size_t)dir * 2 + ((t + 1) & 1)) * (BSZ * HID);

        // prefetch x-projections (independent of h)
        size_t gxbase = ((size_t)dir * SEQ + s) * BSZ * NGATE;
        float gxa[2][4];
#pragma unroll
        for (int u = 0; u < 2; u++) {
            int it = tid + u * 256, b = it >> 3, jj = it & 7;
#pragma unroll
            for (int g = 0; g < 4; g++)
                gxa[u][g] = g_gx[gxbase + (size_t)b * NGATE + g * HID + j0 + jj];
        }

        float acc[2][4];
#pragma unroll
        for (int j = 0; j < 2; j++)
#pragma unroll
            for (int r = 0; r < 4; r++) acc[j][r] = 0.0f;

        // ---- pipelined staging over 8 k-chunks (double-buffered) ----
        uint4 ph[2], pl[2];
#pragma unroll
        for (int e = 0; e < 2; e++) {
            ph[e] = __ldcg((const uint4*)(hp_hi + (size_t)stb * HID + (stq + e) * 8));
            pl[e] = __ldcg((const uint4*)(hp_lo + (size_t)stb * HID + (stq + e) * 8));
        }
#pragma unroll
        for (int e = 0; e < 2; e++) {
            uint32_t off = SWZ128((uint32_t)(stb * 128 + (stq + e) * 16));
            *(uint4*)(dynraw + RH + off) = ph[e];
            *(uint4*)(dynraw + RH + 8192 + off) = pl[e];
        }
#pragma unroll
        for (int e = 0; e < 2; e++) {
            ph[e] = __ldcg((const uint4*)(hp_hi + (size_t)stb * HID + 64 + (stq + e) * 8));
            pl[e] = __ldcg((const uint4*)(hp_lo + (size_t)stb * HID + 64 + (stq + e) * 8));
        }
        __syncthreads();

        for (int kc = 0; kc < 8; kc++) {
            const uint32_t hb = RH + (kc & 1) * 16384;
#pragma unroll
            for (int ks = 0; ks < 4; ks++) {
                const int kb = ks * 32;
                uint32_t ah[4], al[4], bh[4];
                uint32_t aoff = hb + SWZ128((uint32_t)((wm + lm + rplus) * 128 + kb + cplus));
                ldsm_x4(ah, smem + aoff);
                ldsm_x4(al, smem + aoff + 8192);
                uint32_t boff = (uint32_t)(RW + kc * 4096 +
                                SWZ128((wn + lm + rplus) * 128 + kb + cplus));
                ldsm_x4(bh, smem + boff);
                mma16816(acc[0], ah, bh[0], bh[2]);
                mma16816(acc[1], ah, bh[1], bh[3]);
                mma16816(acc[0], al, bh[0], bh[2]);
                mma16816(acc[1], al, bh[1], bh[3]);
            }
            if (kc < 7) {
                const uint32_t nb = RH + ((kc + 1) & 1) * 16384;
#pragma unroll
                for (int e = 0; e < 2; e++) {
                    uint32_t off = SWZ128((uint32_t)(stb * 128 + (stq + e) * 16));
                    *(uint4*)(dynraw + nb + off) = ph[e];
                    *(uint4*)(dynraw + nb + 8192 + off) = pl[e];
                }
                if (kc < 6) {
                    const size_t src = (size_t)stb * HID + (kc + 2) * 64;
#pragma unroll
                    for (int e = 0; e < 2; e++) {
                        ph[e] = __ldcg((const uint4*)(hp_hi + src + (stq + e) * 8));
                        pl[e] = __ldcg((const uint4*)(hp_lo + src + (stq + e) * 8));
                    }
                }
            }
            __syncthreads();
        }

        // ---- exchange preacts via smem ----
#pragma unroll
        for (int j = 0; j < 2; j++) {
            int c = wn + j * 8 + 2 * (lane & 3);
            int b = wm + (lane >> 2);
            *(float2*)(sp + b * 34 + c)       = make_float2(acc[j][0], acc[j][1]);
            *(float2*)(sp + (b + 8) * 34 + c) = make_float2(acc[j][2], acc[j][3]);
        }
        __syncthreads();

        // ---- nonlinearity: 512 (b,jj) items, 2 per thread ----
#pragma unroll
        for (int u = 0; u < 2; u++) {
            int it = tid + u * 256, b = it >> 3, jj = it & 7;
            float f_ = sp[b * 34 + jj]      + gxa[u][0];
            float i_ = sp[b * 34 + 8 + jj]  + gxa[u][1];
            float c_ = sp[b * 34 + 16 + jj] + gxa[u][2];
            float o_ = sp[b * 34 + 24 + jj] + gxa[u][3];
            float fg = 1.0f / (1.0f + __expf(-f_));
            float ig = 1.0f / (1.0f + __expf(-i_));
            float ct = tanhf(c_);
            float og = 1.0f / (1.0f + __expf(-o_));
            float hh = og * tanhf((fg + ig) * ct);      // faithful: c_prev unused
            int j = j0 + jj;
            g_hist[(((size_t)dir * SEQ + s) * BSZ + b) * HID + j] = hh;
            __half hi = __float2half(hh);
            hn_hi[(size_t)b * HID + j] = hi;
            hn_lo[(size_t)b * HID + j] = __float2half(hh - __half2float(hi));
        }

        // ---- split-phase grid barrier: arrive now, wait at loop top ----
        __syncthreads();
        if (tid == 0) {
            __threadfence();
            atomicAdd(&g_cnt[t], 1u);
        }
        __syncthreads();
        if (tid == 0) {
            while (*(volatile unsigned*)&g_cnt[t] < (unsigned)NCTA) { }
        }
        __syncthreads();
    }
}

// ---------------- kernel 5: pooled = max_s tanh(h_fwd * h_bwd) ----------------
__global__ void k_pool() {
    int b = blockIdx.y;
    int h = blockIdx.x * 128 + threadIdx.x;
    float m = -2.0f;
    const float* pf = g_hist + (size_t)b * HID + h;
    const float* pb = g_hist + (size_t)SEQ * BSZ * HID + (size_t)b * HID + h;
    for (int s = 0; s < SEQ; s++) {
        float a = pf[(size_t)s * BSZ * HID];
        float c = pb[(size_t)s * BSZ * HID];
        m = fmaxf(m, tanhf(a * c));
    }
    g_pooled[b * HID + h] = m;
}

// ---------------- kernel 6: out = pooled @ Wout^T + bout ----------------
__global__ void k_out(const float* __restrict__ Wout, const float* __restrict__ bout,
                      float* __restrict__ out) {
    int b = blockIdx.x;
    int c = threadIdx.x >> 5;
    int lane = threadIdx.x & 31;
    float sum = 0.0f;
    for (int h = lane; h < HID; h += 32)
        sum += g_pooled[b * HID + h] * Wout[c * HID + h];
#pragma unroll
    for (int off = 16; off; off >>= 1)
        sum += __shfl_down_sync(0xffffffffu, sum, off);
    if (lane == 0) out[b * CLS + c] = sum + bout[c];
}

// ---------------- launcher ----------------
extern "C" void kernel_launch(void* const* d_in, const int* in_sizes, int n_in,
                              void* d_out, int out_size) {
    const int*   x     = (const int*)d_in[0];
    const float* embed = (const float*)d_in[1];
    const float* fwdW  = (const float*)d_in[2];
    const float* fwdb  = (const float*)d_in[3];
    const float* bwdW  = (const float*)d_in[4];
    const float* bwdb  = (const float*)d_in[5];
    const float* Wout  = (const float*)d_in[6];
    const float* bout  = (const float*)d_in[7];
    float* out = (float*)d_out;

    cudaFuncSetAttribute(k_gemm_fp16, cudaFuncAttributeMaxDynamicSharedMemorySize, GEMM_SMEM);
    cudaFuncSetAttribute(k_recur_mma, cudaFuncAttributeMaxDynamicSharedMemorySize, RECUR_SMEM);

    k_zero<<<512, 256>>>();
    k_splitw<<<NTOT * DHID / 256, 256>>>(fwdW, bwdW);
    k_gather<<<MROWS, 128>>>(x, embed);
    k_gemm_fp16<<<dim3(NTOT / 128, MROWS / 128), 256, GEMM_SMEM>>>(fwdb, bwdb);
    k_recur_mma<<<NCTA, 256, RECUR_SMEM>>>();
    k_pool<<<dim3(HID / 128, BSZ), 128>>>();
    k_out<<<BSZ, CLS * 32>>>(Wout, bout, out);
}

// round 11
// speedup vs baseline: 4.7460x; 1.4486x over previous
#include <cuda_runtime.h>
#include <cuda_fp16.h>
#include <cstdint>

// ---------------- problem constants ----------------
static const int BSZ   = 64;
static const int SEQ   = 256;
static const int DIM   = 512;
static const int HID   = 512;
static const int DHID  = 1024;
static const int NGATE = 2048;              // 4*HID per direction
static const int MROWS = SEQ * BSZ;         // 16384
static const int NTOT  = 4096;              // both directions' gate cols
static const int CLS   = 5;
static const int NCTA  = 128;               // persistent CTAs (<=148 SMs)

// ---------------- device scratch ----------------
__device__ __half g_xh [(size_t)MROWS * DIM];      // embeddings fp16, 16 MB
__device__ __half g_wh [(size_t)NTOT * DHID];      // W fp16, 8 MB
__device__ float  g_gx [2L * SEQ * BSZ * NGATE];   // x-projection + bias
__device__ __half g_hh [2 * 2 * BSZ * HID];        // [dir][parity][b][k] fp16
__device__ float  g_hist[2L * SEQ * BSZ * HID];
__device__ float  g_pooled[BSZ * HID];
__device__ unsigned g_cnt[SEQ];

// ---------------- helpers ----------------
__device__ __forceinline__ uint32_t smem_u32(const void* p) {
    uint32_t a;
    asm("{ .reg .u64 t; cvta.to.shared.u64 t, %1; cvt.u32.u64 %0, t; }" : "=r"(a) : "l"(p));
    return a;
}
#define SWZ128(off) ((off) ^ (((off) >> 3) & 0x70))

__device__ __forceinline__ void ldsm_x4(uint32_t* r, uint32_t addr) {
    asm volatile("ldmatrix.sync.aligned.m8n8.x4.shared.b16 {%0,%1,%2,%3}, [%4];"
                 : "=r"(r[0]), "=r"(r[1]), "=r"(r[2]), "=r"(r[3]) : "r"(addr));
}
// D(16x8 f32) += A(16x16 f16 row) * B(16x8 f16 col)
__device__ __forceinline__ void mma16816(float* d, const uint32_t* a,
                                         uint32_t b0, uint32_t b1) {
    asm volatile(
        "mma.sync.aligned.m16n8k16.row.col.f32.f16.f16.f32 "
        "{%0,%1,%2,%3},{%4,%5,%6,%7},{%8,%9},{%0,%1,%2,%3};"
        : "+f"(d[0]), "+f"(d[1]), "+f"(d[2]), "+f"(d[3])
        : "r"(a[0]), "r"(a[1]), "r"(a[2]), "r"(a[3]), "r"(b0), "r"(b1));
}

extern __shared__ char dynraw[];

// ---------------- kernel 0: zero h plane + barrier counters ----------------
__global__ void k_zero() {
    int i = blockIdx.x * blockDim.x + threadIdx.x;
    if (i < 2 * 2 * BSZ * HID) g_hh[i] = __float2half(0.0f);
    if (i < SEQ) g_cnt[i] = 0u;
}

// ---------------- kernel 1: W -> fp16 --------------------------------------
__global__ void k_splitw(const float* __restrict__ fwdW, const float* __restrict__ bwdW) {
    size_t i = (size_t)blockIdx.x * 256 + threadIdx.x;    // over NTOT*DHID
    int n = (int)(i >> 10), k = (int)(i & 1023);
    int dir = n >> 11, ng = n & 2047;
    g_wh[i] = __float2half((dir ? bwdW : fwdW)[(size_t)ng * DHID + k]);
}

// ---------------- kernel 2: embedding gather -> fp16 ------------------------
__global__ void k_gather(const int* __restrict__ x, const float* __restrict__ embed) {
    int sb = blockIdx.x;                    // sb = s*BSZ + b
    int b = sb & (BSZ - 1);
    int s = sb >> 6;
    int tok = x[b * SEQ + s];
    int c = threadIdx.x * 4;
    float4 v = *(const float4*)(embed + (size_t)tok * DIM + c);
    size_t base = (size_t)sb * DIM + c;
    *(__half2*)(g_xh + base)     = __half2{__float2half(v.x), __float2half(v.y)};
    *(__half2*)(g_xh + base + 2) = __half2{__float2half(v.z), __float2half(v.w)};
}

// ---------------- kernel 3: x-projection GEMM (fp16 mma, 1-pass) -------------
// C[m][n] = sum_k xs[m][k]*W[n][k] + bias(n).  Tile M=128, N=128, Kchunk=64.
static const int SM_A = 0;             // 128 rows x 128B (SW128)
static const int SM_B = 16384;
static const int GEMM_SMEM = 32768;

__global__ void __launch_bounds__(256, 2)
k_gemm_fp16(const float* __restrict__ fwdb, const float* __restrict__ bwdb) {
    const int tid = threadIdx.x, wid = tid >> 5, lane = tid & 31;
    const int m0 = blockIdx.y * 128;
    const int n0 = blockIdx.x * 128;
    const int dir = n0 >> 11, ngbase = n0 & 2047;
    const uint32_t smem = smem_u32(dynraw);

    const int wm = (wid >> 1) * 32;         // warp tile: 32 m x 64 n
    const int wn = (wid & 1) * 64;

    const int lm  = lane & 7;
    const int sel = lane >> 3;
    const int rplus = (sel & 1) * 8;
    const int cplus = (sel >> 1) * 16;      // bytes

    const int srow = tid >> 3, sc16 = tid & 7;

    float acc[2][8][4];
#pragma unroll
    for (int i = 0; i < 2; i++)
#pragma unroll
        for (int j = 0; j < 8; j++)
#pragma unroll
            for (int r = 0; r < 4; r++) acc[i][j][r] = 0.0f;

    for (int kc = 0; kc < 8; kc++) {
        const int k0 = kc * 64;
#pragma unroll
        for (int it = 0; it < 4; it++) {
            int row = srow + it * 32;
            uint32_t off = SWZ128((uint32_t)(row * 128 + sc16 * 16));
            size_t ga = (size_t)(m0 + row) * DIM + k0 + sc16 * 8;
            size_t gb = (size_t)(n0 + row) * DHID + k0 + sc16 * 8;
            *(uint4*)(dynraw + SM_A + off) = *(const uint4*)(g_xh + ga);
            *(uint4*)(dynraw + SM_B + off) = *(const uint4*)(g_wh + gb);
        }
        __syncthreads();

#pragma unroll
        for (int ks = 0; ks < 4; ks++) {
            const int kb = ks * 32;
            uint32_t a[2][4];
#pragma unroll
            for (int i = 0; i < 2; i++) {
                uint32_t off = SWZ128((uint32_t)((wm + i * 16 + lm + rplus) * 128 + kb + cplus));
                ldsm_x4(a[i], smem + SM_A + off);
            }
#pragma unroll
            for (int j = 0; j < 4; j++) {
                uint32_t off = SWZ128((uint32_t)((wn + j * 16 + lm + rplus) * 128 + kb + cplus));
                uint32_t bh[4];
                ldsm_x4(bh, smem + SM_B + off);
#pragma unroll
                for (int i = 0; i < 2; i++) {
                    mma16816(acc[i][j * 2],     a[i], bh[0], bh[2]);
                    mma16816(acc[i][j * 2 + 1], a[i], bh[1], bh[3]);
                }
            }
        }
        __syncthreads();
    }

    const float* bv = dir ? bwdb : fwdb;
    const size_t dirbase = (size_t)dir * SEQ * BSZ * NGATE;
#pragma unroll
    for (int i = 0; i < 2; i++) {
        int mr0 = m0 + wm + i * 16 + (lane >> 2);
#pragma unroll
        for (int j = 0; j < 8; j++) {
            int ng = ngbase + wn + j * 8 + 2 * (lane & 3);
            float2 bb = *(const float2*)(bv + ng);
            *(float2*)(g_gx + dirbase + (size_t)mr0 * NGATE + ng) =
                make_float2(acc[i][j][0] + bb.x, acc[i][j][1] + bb.y);
            *(float2*)(g_gx + dirbase + (size_t)(mr0 + 8) * NGATE + ng) =
                make_float2(acc[i][j][2] + bb.x, acc[i][j][3] + bb.y);
        }
    }
}

// ---------------- kernel 4: persistent recurrence (fp16, single-buffer) -----
// 128 CTAs: dir = bid>>6, j0 = (bid&63)*8 -> 32 gate cols x 64 batch, K=512.
// W slice resident; full h plane staged once per step (one sync), mma sync-free.
static const int RW  = 0;               // 8 kc x 32 rows x 128B = 32 KB
static const int RH  = 32768;           // 8 kc x 64 rows x 128B = 64 KB
static const int RSP = 98304;           // 64 x 34 floats exchange
static const int RECUR_SMEM = RSP + BSZ * 34 * 4;   // 107008 B

__global__ void __launch_bounds__(256, 1)
k_recur_mma() {
    const int bid = blockIdx.x;
    const int dir = bid >> 6;
    const int j0 = (bid & 63) * 8;
    const int tid = threadIdx.x, wid = tid >> 5, lane = tid & 31;
    const uint32_t smem = smem_u32(dynraw);

    const int lm  = lane & 7;
    const int sel = lane >> 3;
    const int rplus = (sel & 1) * 8;
    const int cplus = (sel >> 1) * 16;
    const int wm = (wid >> 1) * 16;          // batch tile base
    const int wn = (wid & 1) * 16;           // col tile base
    float* sp = (float*)(dynraw + RSP);

    // ---- preload W slice (k in [512,1024)), SW128 per 64-k chunk ----
#pragma unroll
    for (int it = 0; it < 8; it++) {
        int idx = it * 256 + tid;            // 2048 chunks
        int c = idx >> 6, c16 = idx & 63;
        int kc = c16 >> 3;
        int n = dir * 2048 + (c >> 3) * HID + j0 + (c & 7);
        uint32_t off = (uint32_t)(kc * 4096 + SWZ128(c * 128 + (c16 & 7) * 16));
        *(uint4*)(dynraw + RW + off) = *(const uint4*)(g_wh + (size_t)n * DHID + 512 + c16 * 8);
    }
    __syncthreads();

    for (int t = 0; t < SEQ; t++) {
        const int s = dir ? (SEQ - 1 - t) : t;
        const __half* hp = g_hh + ((size_t)dir * 2 + (t & 1)) * (BSZ * HID);
        __half*       hn = g_hh + ((size_t)dir * 2 + ((t + 1) & 1)) * (BSZ * HID);

        // ---- stage full h plane: 4096 16B chunks, 16 per thread (L2 loads) ----
        uint4 pre[16];
#pragma unroll
        for (int it = 0; it < 16; it++) {
            int idx = it * 256 + tid;
            int b = idx >> 6, c16 = idx & 63;
            pre[it] = __ldcg((const uint4*)(hp + (size_t)b * HID + c16 * 8));
        }
        // prefetch x-projections while loads are in flight
        size_t gxbase = ((size_t)dir * SEQ + s) * BSZ * NGATE;
        float gxa[2][4];
#pragma unroll
        for (int u = 0; u < 2; u++) {
            int it = tid + u * 256, b = it >> 3, jj = it & 7;
#pragma unroll
            for (int g = 0; g < 4; g++)
                gxa[u][g] = g_gx[gxbase + (size_t)b * NGATE + g * HID + j0 + jj];
        }
#pragma unroll
        for (int it = 0; it < 16; it++) {
            int idx = it * 256 + tid;
            int b = idx >> 6, c16 = idx & 63;
            int kc = c16 >> 3;
            uint32_t off = (uint32_t)(kc * 8192 + SWZ128(b * 128 + (c16 & 7) * 16));
            *(uint4*)(dynraw + RH + off) = pre[it];
        }
        __syncthreads();

        float acc[2][4];
#pragma unroll
        for (int j = 0; j < 2; j++)
#pragma unroll
            for (int r = 0; r < 4; r++) acc[j][r] = 0.0f;

#pragma unroll 4
        for (int kc = 0; kc < 8; kc++) {
#pragma unroll
            for (int ks = 0; ks < 4; ks++) {
                const int kb = ks * 32;
                uint32_t ah[4], bh[4];
                uint32_t aoff = (uint32_t)(RH + kc * 8192 +
                                SWZ128((wm + lm + rplus) * 128 + kb + cplus));
                ldsm_x4(ah, smem + aoff);
                uint32_t boff = (uint32_t)(RW + kc * 4096 +
                                SWZ128((wn + lm + rplus) * 128 + kb + cplus));
                ldsm_x4(bh, smem + boff);
                mma16816(acc[0], ah, bh[0], bh[2]);
                mma16816(acc[1], ah, bh[1], bh[3]);
            }
        }

        // ---- exchange preacts via smem ----
#pragma unroll
        for (int j = 0; j < 2; j++) {
            int c = wn + j * 8 + 2 * (lane & 3);
            int b = wm + (lane >> 2);
            *(float2*)(sp + b * 34 + c)       = make_float2(acc[j][0], acc[j][1]);
            *(float2*)(sp + (b + 8) * 34 + c) = make_float2(acc[j][2], acc[j][3]);
        }
        __syncthreads();

        // ---- nonlinearity: 512 (b,jj) items, 2 per thread ----
#pragma unroll
        for (int u = 0; u < 2; u++) {
            int it = tid + u * 256, b = it >> 3, jj = it & 7;
            float f_ = sp[b * 34 + jj]      + gxa[u][0];
            float i_ = sp[b * 34 + 8 + jj]  + gxa[u][1];
            float c_ = sp[b * 34 + 16 + jj] + gxa[u][2];
            float o_ = sp[b * 34 + 24 + jj] + gxa[u][3];
            float fg = 1.0f / (1.0f + __expf(-f_));
            float ig = 1.0f / (1.0f + __expf(-i_));
            float ct = tanhf(c_);
            float og = 1.0f / (1.0f + __expf(-o_));
            float hh = og * tanhf((fg + ig) * ct);      // faithful: c_prev unused
            int j = j0 + jj;
            g_hist[(((size_t)dir * SEQ + s) * BSZ + b) * HID + j] = hh;
            hn[(size_t)b * HID + j] = __float2half(hh);
        }

        // ---- split-phase grid barrier ----
        __syncthreads();
        if (tid == 0) {
            __threadfence();
            atomicAdd(&g_cnt[t], 1u);
            while (*(volatile unsigned*)&g_cnt[t] < (unsigned)NCTA) { }
        }
        __syncthreads();
    }
}

// ---------------- kernel 5: pooled = max_s tanh(h_fwd * h_bwd) ----------------
__global__ void k_pool() {
    int b = blockIdx.y;
    int h = blockIdx.x * 128 + threadIdx.x;
    float m = -2.0f;
    const float* pf = g_hist + (size_t)b * HID + h;
    const float* pb = g_hist + (size_t)SEQ * BSZ * HID + (size_t)b * HID + h;
    for (int s = 0; s < SEQ; s++) {
        float a = pf[(size_t)s * BSZ * HID];
        float c = pb[(size_t)s * BSZ * HID];
        m = fmaxf(m, tanhf(a * c));
    }
    g_pooled[b * HID + h] = m;
}

// ---------------- kernel 6: out = pooled @ Wout^T + bout ----------------
__global__ void k_out(const float* __restrict__ Wout, const float* __restrict__ bout,
                      float* __restrict__ out) {
    int b = blockIdx.x;
    int c = threadIdx.x >> 5;
    int lane = threadIdx.x & 31;
    float sum = 0.0f;
    for (int h = lane; h < HID; h += 32)
        sum += g_pooled[b * HID + h] * Wout[c * HID + h];
#pragma unroll
    for (int off = 16; off; off >>= 1)
        sum += __shfl_down_sync(0xffffffffu, sum, off);
    if (lane == 0) out[b * CLS + c] = sum + bout[c];
}

// ---------------- launcher ----------------
extern "C" void kernel_launch(void* const* d_in, const int* in_sizes, int n_in,
                              void* d_out, int out_size) {
    const int*   x     = (const int*)d_in[0];
    const float* embed = (const float*)d_in[1];
    const float* fwdW  = (const float*)d_in[2];
    const float* fwdb  = (const float*)d_in[3];
    const float* bwdW  = (const float*)d_in[4];
    const float* bwdb  = (const float*)d_in[5];
    const float* Wout  = (const float*)d_in[6];
    const float* bout  = (const float*)d_in[7];
    float* out = (float*)d_out;

    cudaFuncSetAttribute(k_gemm_fp16, cudaFuncAttributeMaxDynamicSharedMemorySize, GEMM_SMEM);
    cudaFuncSetAttribute(k_recur_mma, cudaFuncAttributeMaxDynamicSharedMemorySize, RECUR_SMEM);

    k_zero<<<512, 256>>>();
    k_splitw<<<NTOT * DHID / 256, 256>>>(fwdW, bwdW);
    k_gather<<<MROWS, 128>>>(x, embed);
    k_gemm_fp16<<<dim3(NTOT / 128, MROWS / 128), 256, GEMM_SMEM>>>(fwdb, bwdb);
    k_recur_mma<<<NCTA, 256, RECUR_SMEM>>>();
    k_pool<<<dim3(HID / 128, BSZ), 128>>>();
    k_out<<<BSZ, CLS * 32>>>(Wout, bout, out);
}

// round 12
// speedup vs baseline: 4.9188x; 1.0364x over previous
#include <cuda_runtime.h>
#include <cuda_fp16.h>
#include <cstdint>

// ---------------- problem constants ----------------
static const int BSZ   = 64;
static const int SEQ   = 256;
static const int DIM   = 512;
static const int HID   = 512;
static const int DHID  = 1024;
static const int NGATE = 2048;              // 4*HID per direction
static const int MROWS = SEQ * BSZ;         // 16384
static const int NTOT  = 4096;              // both directions' gate cols
static const int CLS   = 5;
static const int NCTA  = 128;               // persistent CTAs (<=148 SMs)

// ---------------- device scratch ----------------
__device__ __half g_xh [(size_t)MROWS * DIM];      // embeddings fp16, 16 MB
__device__ __half g_wh [(size_t)NTOT * DHID];      // W fp16, 8 MB
__device__ float  g_gx [2L * SEQ * BSZ * NGATE];   // x-projection + bias
__device__ __half g_hh [2 * 2 * BSZ * HID];        // [dir][parity][b][k] fp16
__device__ __half g_hist[2L * SEQ * BSZ * HID];    // fp16 history, 33.5 MB
__device__ float  g_pooled[BSZ * HID];
__device__ unsigned g_cnt[SEQ];

// ---------------- helpers ----------------
__device__ __forceinline__ uint32_t smem_u32(const void* p) {
    uint32_t a;
    asm("{ .reg .u64 t; cvta.to.shared.u64 t, %1; cvt.u32.u64 %0, t; }" : "=r"(a) : "l"(p));
    return a;
}
#define SWZ128(off) ((off) ^ (((off) >> 3) & 0x70))

#define CP_ASYNC16(sa, gp) \
    asm volatile("cp.async.cg.shared.global [%0], [%1], 16;" :: "r"((uint32_t)(sa)), "l"(gp))
#define CP_COMMIT() asm volatile("cp.async.commit_group;" ::: "memory")
#define CP_WAIT0()  asm volatile("cp.async.wait_group 0;" ::: "memory")
#define CP_WAIT1()  asm volatile("cp.async.wait_group 1;" ::: "memory")

__device__ __forceinline__ void ldsm_x4(uint32_t* r, uint32_t addr) {
    asm volatile("ldmatrix.sync.aligned.m8n8.x4.shared.b16 {%0,%1,%2,%3}, [%4];"
                 : "=r"(r[0]), "=r"(r[1]), "=r"(r[2]), "=r"(r[3]) : "r"(addr));
}
// D(16x8 f32) += A(16x16 f16 row) * B(16x8 f16 col)
__device__ __forceinline__ void mma16816(float* d, const uint32_t* a,
                                         uint32_t b0, uint32_t b1) {
    asm volatile(
        "mma.sync.aligned.m16n8k16.row.col.f32.f16.f16.f32 "
        "{%0,%1,%2,%3},{%4,%5,%6,%7},{%8,%9},{%0,%1,%2,%3};"
        : "+f"(d[0]), "+f"(d[1]), "+f"(d[2]), "+f"(d[3])
        : "r"(a[0]), "r"(a[1]), "r"(a[2]), "r"(a[3]), "r"(b0), "r"(b1));
}

extern __shared__ char dynraw[];

// ---------------- kernel 0: zero h plane + barrier counters ----------------
__global__ void k_zero() {
    int i = blockIdx.x * blockDim.x + threadIdx.x;
    if (i < 2 * 2 * BSZ * HID) g_hh[i] = __float2half(0.0f);
    if (i < SEQ) g_cnt[i] = 0u;
}

// ---------------- kernel 1: W -> fp16 --------------------------------------
__global__ void k_splitw(const float* __restrict__ fwdW, const float* __restrict__ bwdW) {
    size_t i = (size_t)blockIdx.x * 256 + threadIdx.x;    // over NTOT*DHID
    int n = (int)(i >> 10), k = (int)(i & 1023);
    int dir = n >> 11, ng = n & 2047;
    g_wh[i] = __float2half((dir ? bwdW : fwdW)[(size_t)ng * DHID + k]);
}

// ---------------- kernel 2: embedding gather -> fp16 ------------------------
__global__ void k_gather(const int* __restrict__ x, const float* __restrict__ embed) {
    int sb = blockIdx.x;                    // sb = s*BSZ + b
    int b = sb & (BSZ - 1);
    int s = sb >> 6;
    int tok = x[b * SEQ + s];
    int c = threadIdx.x * 4;
    float4 v = *(const float4*)(embed + (size_t)tok * DIM + c);
    size_t base = (size_t)sb * DIM + c;
    *(__half2*)(g_xh + base)     = __half2{__float2half(v.x), __float2half(v.y)};
    *(__half2*)(g_xh + base + 2) = __half2{__float2half(v.z), __float2half(v.w)};
}

// ---------------- kernel 3: x-proj GEMM (fp16 mma, cp.async 2-stage) --------
// C[m][n] = sum_k xs[m][k]*W[n][k] + bias(n).  Tile M=128, N=128, Kchunk=64.
static const int GSTG = 32768;          // per stage: A 16KB + B 16KB
static const int GEMM_SMEM = 65536;

__global__ void __launch_bounds__(256, 2)
k_gemm_fp16(const float* __restrict__ fwdb, const float* __restrict__ bwdb) {
    const int tid = threadIdx.x, wid = tid >> 5, lane = tid & 31;
    const int m0 = blockIdx.y * 128;
    const int n0 = blockIdx.x * 128;
    const int dir = n0 >> 11, ngbase = n0 & 2047;
    const uint32_t smem = smem_u32(dynraw);

    const int wm = (wid >> 1) * 32;         // warp tile: 32 m x 64 n
    const int wn = (wid & 1) * 64;

    const int lm  = lane & 7;
    const int sel = lane >> 3;
    const int rplus = (sel & 1) * 8;
    const int cplus = (sel >> 1) * 16;      // bytes

    const int srow = tid >> 3, sc16 = tid & 7;

    float acc[2][8][4];
#pragma unroll
    for (int i = 0; i < 2; i++)
#pragma unroll
        for (int j = 0; j < 8; j++)
#pragma unroll
            for (int r = 0; r < 4; r++) acc[i][j][r] = 0.0f;

    // ---- issue stage for k-chunk kc ----
    auto issue = [&](int kc) {
        const int k0 = kc * 64;
        const uint32_t sbase = smem + (kc & 1) * GSTG;
#pragma unroll
        for (int it = 0; it < 4; it++) {
            int row = srow + it * 32;
            uint32_t off = SWZ128((uint32_t)(row * 128 + sc16 * 16));
            CP_ASYNC16(sbase + off,         g_xh + (size_t)(m0 + row) * DIM + k0 + sc16 * 8);
            CP_ASYNC16(sbase + 16384 + off, g_wh + (size_t)(n0 + row) * DHID + k0 + sc16 * 8);
        }
        CP_COMMIT();
    };

    issue(0);
    for (int kc = 0; kc < 8; kc++) {
        if (kc < 7) { issue(kc + 1); CP_WAIT1(); } else { CP_WAIT0(); }
        __syncthreads();
        const uint32_t abase = smem + (kc & 1) * GSTG;
        const uint32_t bbase = abase + 16384;
#pragma unroll
        for (int ks = 0; ks < 4; ks++) {
            const int kb = ks * 32;
            uint32_t a[2][4];
#pragma unroll
            for (int i = 0; i < 2; i++) {
                uint32_t off = SWZ128((uint32_t)((wm + i * 16 + lm + rplus) * 128 + kb + cplus));
                ldsm_x4(a[i], abase + off);
            }
#pragma unroll
            for (int j = 0; j < 4; j++) {
                uint32_t off = SWZ128((uint32_t)((wn + j * 16 + lm + rplus) * 128 + kb + cplus));
                uint32_t bh[4];
                ldsm_x4(bh, bbase + off);
#pragma unroll
                for (int i = 0; i < 2; i++) {
                    mma16816(acc[i][j * 2],     a[i], bh[0], bh[2]);
                    mma16816(acc[i][j * 2 + 1], a[i], bh[1], bh[3]);
                }
            }
        }
        __syncthreads();
    }

    const float* bv = dir ? bwdb : fwdb;
    const size_t dirbase = (size_t)dir * SEQ * BSZ * NGATE;
#pragma unroll
    for (int i = 0; i < 2; i++) {
        int mr0 = m0 + wm + i * 16 + (lane >> 2);
#pragma unroll
        for (int j = 0; j < 8; j++) {
            int ng = ngbase + wn + j * 8 + 2 * (lane & 3);
            float2 bb = *(const float2*)(bv + ng);
            *(float2*)(g_gx + dirbase + (size_t)mr0 * NGATE + ng) =
                make_float2(acc[i][j][0] + bb.x, acc[i][j][1] + bb.y);
            *(float2*)(g_gx + dirbase + (size_t)(mr0 + 8) * NGATE + ng) =
                make_float2(acc[i][j][2] + bb.x, acc[i][j][3] + bb.y);
        }
    }
}

// ---------------- kernel 4: persistent recurrence (fp16, cp.async staging) --
// 128 CTAs: dir = bid>>6, j0 = (bid&63)*8 -> 32 gate cols x 64 batch, K=512.
static const int RW  = 0;               // 8 kc x 32 rows x 128B = 32 KB
static const int RH  = 32768;           // 8 kc x 64 rows x 128B = 64 KB
static const int RSP = 98304;           // 64 x 34 floats exchange
static const int RECUR_SMEM = RSP + BSZ * 34 * 4;   // 107008 B

__global__ void __launch_bounds__(256, 1)
k_recur_mma() {
    const int bid = blockIdx.x;
    const int dir = bid >> 6;
    const int j0 = (bid & 63) * 8;
    const int tid = threadIdx.x, wid = tid >> 5, lane = tid & 31;
    const uint32_t smem = smem_u32(dynraw);

    const int lm  = lane & 7;
    const int sel = lane >> 3;
    const int rplus = (sel & 1) * 8;
    const int cplus = (sel >> 1) * 16;
    const int wm = (wid >> 1) * 16;          // batch tile base
    const int wn = (wid & 1) * 16;           // col tile base
    float* sp = (float*)(dynraw + RSP);

    // ---- preload W slice (k in [512,1024)), SW128 per 64-k chunk ----
#pragma unroll
    for (int it = 0; it < 8; it++) {
        int idx = it * 256 + tid;            // 2048 chunks
        int c = idx >> 6, c16 = idx & 63;
        int kc = c16 >> 3;
        int n = dir * 2048 + (c >> 3) * HID + j0 + (c & 7);
        uint32_t off = (uint32_t)(kc * 4096 + SWZ128(c * 128 + (c16 & 7) * 16));
        *(uint4*)(dynraw + RW + off) = *(const uint4*)(g_wh + (size_t)n * DHID + 512 + c16 * 8);
    }
    __syncthreads();

    for (int t = 0; t < SEQ; t++) {
        const int s = dir ? (SEQ - 1 - t) : t;
        const __half* hp = g_hh + ((size_t)dir * 2 + (t & 1)) * (BSZ * HID);
        __half*       hn = g_hh + ((size_t)dir * 2 + ((t + 1) & 1)) * (BSZ * HID);

        // ---- stage full h plane via cp.async.cg (L2 path; bypasses stale L1) ----
#pragma unroll
        for (int it = 0; it < 16; it++) {
            int idx = it * 256 + tid;
            int b = idx >> 6, c16 = idx & 63;
            int kc = c16 >> 3;
            uint32_t off = (uint32_t)(RH + kc * 8192 + SWZ128(b * 128 + (c16 & 7) * 16));
            CP_ASYNC16(smem + off, hp + (size_t)b * HID + c16 * 8);
        }
        CP_COMMIT();

        // prefetch x-projections while copies are in flight
        size_t gxbase = ((size_t)dir * SEQ + s) * BSZ * NGATE;
        float gxa[2][4];
#pragma unroll
        for (int u = 0; u < 2; u++) {
            int it = tid + u * 256, b = it >> 3, jj = it & 7;
#pragma unroll
            for (int g = 0; g < 4; g++)
                gxa[u][g] = g_gx[gxbase + (size_t)b * NGATE + g * HID + j0 + jj];
        }

        CP_WAIT0();
        __syncthreads();

        float acc[2][4];
#pragma unroll
        for (int j = 0; j < 2; j++)
#pragma unroll
            for (int r = 0; r < 4; r++) acc[j][r] = 0.0f;

#pragma unroll 4
        for (int kc = 0; kc < 8; kc++) {
#pragma unroll
            for (int ks = 0; ks < 4; ks++) {
                const int kb = ks * 32;
                uint32_t ah[4], bh[4];
                uint32_t aoff = (uint32_t)(RH + kc * 8192 +
                                SWZ128((wm + lm + rplus) * 128 + kb + cplus));
                ldsm_x4(ah, smem + aoff);
                uint32_t boff = (uint32_t)(RW + kc * 4096 +
                                SWZ128((wn + lm + rplus) * 128 + kb + cplus));
                ldsm_x4(bh, smem + boff);
                mma16816(acc[0], ah, bh[0], bh[2]);
                mma16816(acc[1], ah, bh[1], bh[3]);
            }
        }

        // ---- exchange preacts via smem ----
#pragma unroll
        for (int j = 0; j < 2; j++) {
            int c = wn + j * 8 + 2 * (lane & 3);
            int b = wm + (lane >> 2);
            *(float2*)(sp + b * 34 + c)       = make_float2(acc[j][0], acc[j][1]);
            *(float2*)(sp + (b + 8) * 34 + c) = make_float2(acc[j][2], acc[j][3]);
        }
        __syncthreads();

        // ---- nonlinearity: 512 (b,jj) items, 2 per thread ----
#pragma unroll
        for (int u = 0; u < 2; u++) {
            int it = tid + u * 256, b = it >> 3, jj = it & 7;
            float f_ = sp[b * 34 + jj]      + gxa[u][0];
            float i_ = sp[b * 34 + 8 + jj]  + gxa[u][1];
            float c_ = sp[b * 34 + 16 + jj] + gxa[u][2];
            float o_ = sp[b * 34 + 24 + jj] + gxa[u][3];
            float fg = 1.0f / (1.0f + __expf(-f_));
            float ig = 1.0f / (1.0f + __expf(-i_));
            float ct = tanhf(c_);
            float og = 1.0f / (1.0f + __expf(-o_));
            float hh = og * tanhf((fg + ig) * ct);      // faithful: c_prev unused
            int j = j0 + jj;
            __half hq = __float2half(hh);
            g_hist[(((size_t)dir * SEQ + s) * BSZ + b) * HID + j] = hq;
            hn[(size_t)b * HID + j] = hq;
        }

        // ---- grid barrier (all 128 CTAs resident) ----
        __syncthreads();
        if (tid == 0) {
            __threadfence();
            atomicAdd(&g_cnt[t], 1u);
            while (*(volatile unsigned*)&g_cnt[t] < (unsigned)NCTA) { }
        }
        __syncthreads();
    }
}

// ---------------- kernel 5: pooled = tanh(max_s (hf*hb))  [tanh monotonic] --
__global__ void k_pool() {
    int b = blockIdx.y;
    int h2 = blockIdx.x * 128 + threadIdx.x;     // half2 index, 0..255
    const __half2* pf = (const __half2*)g_hist + (size_t)b * (HID / 2) + h2;
    const __half2* pb = pf + (size_t)SEQ * BSZ * (HID / 2);
    float2 m = make_float2(-1e30f, -1e30f);
#pragma unroll 4
    for (int s = 0; s < SEQ; s++) {
        float2 a = __half22float2(pf[(size_t)s * BSZ * (HID / 2)]);
        float2 c = __half22float2(pb[(size_t)s * BSZ * (HID / 2)]);
        m.x = fmaxf(m.x, a.x * c.x);
        m.y = fmaxf(m.y, a.y * c.y);
    }
    *(float2*)(g_pooled + b * HID + 2 * h2) = make_float2(tanhf(m.x), tanhf(m.y));
}

// ---------------- kernel 6: out = pooled @ Wout^T + bout ----------------
__global__ void k_out(const float* __restrict__ Wout, const float* __restrict__ bout,
                      float* __restrict__ out) {
    int b = blockIdx.x;
    int c = threadIdx.x >> 5;
    int lane = threadIdx.x & 31;
    float sum = 0.0f;
    for (int h = lane; h < HID; h += 32)
        sum += g_pooled[b * HID + h] * Wout[c * HID + h];
#pragma unroll
    for (int off = 16; off; off >>= 1)
        sum += __shfl_down_sync(0xffffffffu, sum, off);
    if (lane == 0) out[b * CLS + c] = sum + bout[c];
}

// ---------------- launcher ----------------
extern "C" void kernel_launch(void* const* d_in, const int* in_sizes, int n_in,
                              void* d_out, int out_size) {
    const int*   x     = (const int*)d_in[0];
    const float* embed = (const float*)d_in[1];
    const float* fwdW  = (const float*)d_in[2];
    const float* fwdb  = (const float*)d_in[3];
    const float* bwdW  = (const float*)d_in[4];
    const float* bwdb  = (const float*)d_in[5];
    const float* Wout  = (const float*)d_in[6];
    const float* bout  = (const float*)d_in[7];
    float* out = (float*)d_out;

    cudaFuncSetAttribute(k_gemm_fp16, cudaFuncAttributeMaxDynamicSharedMemorySize, GEMM_SMEM);
    cudaFuncSetAttribute(k_recur_mma, cudaFuncAttributeMaxDynamicSharedMemorySize, RECUR_SMEM);

    k_zero<<<512, 256>>>();
    k_splitw<<<NTOT * DHID / 256, 256>>>(fwdW, bwdW);
    k_gather<<<MROWS, 128>>>(x, embed);
    k_gemm_fp16<<<dim3(NTOT / 128, MROWS / 128), 256, GEMM_SMEM>>>(fwdb, bwdb);
    k_recur_mma<<<NCTA, 256, RECUR_SMEM>>>();
    k_pool<<<dim3(HID / 256, BSZ), 128>>>();
    k_out<<<BSZ, CLS * 32>>>(Wout, bout, out);
}